// round 6
// baseline (speedup 1.0000x reference)
#include <cuda_runtime.h>
#include <cstddef>

// ---------------- problem constants ----------------
#define NW    8192          // words
#define LW    24            // chars per word
#define D     256           // model dim
#define NH    8             // heads
#define HD    32            // head dim
#define DFF   1024
#define NC    1024          // concepts
#define MAXW  16
#define M1    (NW*LW)       // 196608 tokens, block 1
#define M2    (NC*MAXW)     // 16384 tokens, block 2

// ---------------- scratch (device globals; no cudaMalloc allowed) ----------------
__device__ float g_x   [(size_t)M1*D];      // embeddings / word_ft
__device__ float g_qkv [(size_t)M1*3*D];    // fused qkv
__device__ float g_attn[(size_t)M1*D];      // attention out / name_ft
__device__ float g_t   [(size_t)M1*D];      // gemm temp (o-proj / ff2 out)
__device__ float g_h   [(size_t)M1*D];      // post-attn LN
__device__ float g_ff  [(size_t)M1*DFF];    // ff intermediate
__device__ float g_pad [(size_t)M2*D];      // padded [NC, MAXW, D]

// ---------------- embedding gather ----------------
__global__ void embed_k(const int* __restrict__ toks, const float* __restrict__ emb,
                        float* __restrict__ x, int total) {
    int i = blockIdx.x * blockDim.x + threadIdx.x;
    if (i < total) {
        int tok = toks[i >> 8];           // i / D
        x[i] = emb[tok * D + (i & 255)];  // i % D
    }
}

__global__ void zero_k(float* __restrict__ p, int n) {
    int i = blockIdx.x * blockDim.x + threadIdx.x;
    if (i < n) p[i] = 0.f;
}

// ---------------- fp32 SGEMM: C[M,N] = op(A[M,K] @ B[K,N]) ----------------
// 128x128 block tile, BK=8, 256 threads, 8x8 per-thread tile.
// Requires M%128==0, N%128==0, K%8==0 (true for all shapes here).
template<bool RELU>
__global__ void __launch_bounds__(256) sgemm_k(const float* __restrict__ A,
                                               const float* __restrict__ B,
                                               float* __restrict__ C,
                                               int M, int N, int K) {
    __shared__ float As[8][128];
    __shared__ float Bs[8][128];
    const int bm = blockIdx.y * 128;
    const int bn = blockIdx.x * 128;
    const int t  = threadIdx.x;

    const int arow = t >> 1, ac4 = (t & 1) * 4;   // A: 128 rows x 8 cols (2 float4/row)
    const int brow = t >> 5, bc4 = (t & 31) * 4;  // B: 8 rows x 128 cols
    const int rb = (t >> 4) * 8;                  // output row base within tile
    const int cb = (t & 15) * 8;                  // output col base within tile

    float acc[8][8];
    #pragma unroll
    for (int i = 0; i < 8; i++)
        #pragma unroll
        for (int j = 0; j < 8; j++) acc[i][j] = 0.f;

    for (int k0 = 0; k0 < K; k0 += 8) {
        float4 av = *(const float4*)(A + (size_t)(bm + arow) * K + k0 + ac4);
        As[ac4 + 0][arow] = av.x;
        As[ac4 + 1][arow] = av.y;
        As[ac4 + 2][arow] = av.z;
        As[ac4 + 3][arow] = av.w;
        *(float4*)&Bs[brow][bc4] =
            *(const float4*)(B + (size_t)(k0 + brow) * N + bn + bc4);
        __syncthreads();

        #pragma unroll
        for (int k = 0; k < 8; k++) {
            float ra[8], rbv[8];
            *(float4*)&ra[0]  = *(float4*)&As[k][rb];
            *(float4*)&ra[4]  = *(float4*)&As[k][rb + 4];
            *(float4*)&rbv[0] = *(float4*)&Bs[k][cb];
            *(float4*)&rbv[4] = *(float4*)&Bs[k][cb + 4];
            #pragma unroll
            for (int i = 0; i < 8; i++)
                #pragma unroll
                for (int j = 0; j < 8; j++) acc[i][j] += ra[i] * rbv[j];
        }
        __syncthreads();
    }

    #pragma unroll
    for (int i = 0; i < 8; i++) {
        float out[8];
        #pragma unroll
        for (int j = 0; j < 8; j++)
            out[j] = RELU ? fmaxf(acc[i][j], 0.f) : acc[i][j];
        float* cp = C + (size_t)(bm + rb + i) * N + bn + cb;
        *(float4*)cp       = *(float4*)&out[0];
        *(float4*)(cp + 4) = *(float4*)&out[4];
    }
}

// ---------------- attention: one block per word, one warp per head ----------------
// smem holds the word's full fused QKV [LT, 768]. Lane l < LT owns query row l.
template<int LT, bool MASKED>
__global__ void __launch_bounds__(256) attn_k(const float* __restrict__ qkv,
                                              const int* __restrict__ toks,
                                              float* __restrict__ out) {
    extern __shared__ float s[];   // LT * 768 floats
    __shared__ int smask[32];
    const int w = blockIdx.x, tid = threadIdx.x;

    const float4* base = (const float4*)(qkv + (size_t)w * LT * 768);
    float4* s4 = (float4*)s;
    for (int i = tid; i < LT * 192; i += 256) s4[i] = base[i];
    if (MASKED) {
        if (tid < LT) smask[tid] = (toks[(size_t)w * LT + tid] == 0);
    }
    __syncthreads();

    const int h = tid >> 5, lane = tid & 31;
    if (lane < LT) {
        float q[HD];
        const float* qp = s + lane * 768 + h * HD;
        #pragma unroll
        for (int d = 0; d < HD; d++) q[d] = qp[d];

        float p[LT];
        float mx = -1e30f;
        #pragma unroll
        for (int j = 0; j < LT; j++) {
            const float* kp = s + j * 768 + 256 + h * HD;
            float a = 0.f;
            #pragma unroll
            for (int d = 0; d < HD; d++) a += q[d] * kp[d];
            a *= 0.17677669529663687f;   // 1/sqrt(32)
            if (MASKED && smask[j]) a = -1e9f;
            p[j] = a;
            mx = fmaxf(mx, a);
        }
        float sum = 0.f;
        #pragma unroll
        for (int j = 0; j < LT; j++) { p[j] = expf(p[j] - mx); sum += p[j]; }
        const float inv = 1.f / sum;

        float* op = out + ((size_t)w * LT + lane) * D + h * HD;
        #pragma unroll
        for (int d = 0; d < HD; d++) {
            float a = 0.f;
            #pragma unroll
            for (int j = 0; j < LT; j++) a += p[j] * s[j * 768 + 512 + h * HD + d];
            op[d] = a * inv;
        }
    }
}

// ---------------- residual add + LayerNorm (no affine), one block per row ----------------
__global__ void __launch_bounds__(256) addln_k(const float* __restrict__ a,
                                               const float* __restrict__ b,
                                               float* __restrict__ o) {
    const int row = blockIdx.x, tid = threadIdx.x;
    const size_t idx = (size_t)row * D + tid;
    const float v = a[idx] + b[idx];

    __shared__ float red[8];
    float s = v;
    #pragma unroll
    for (int off = 16; off; off >>= 1) s += __shfl_xor_sync(0xffffffffu, s, off);
    if ((tid & 31) == 0) red[tid >> 5] = s;
    __syncthreads();
    float tot = 0.f;
    #pragma unroll
    for (int i = 0; i < 8; i++) tot += red[i];
    const float mean = tot * (1.f / 256.f);
    const float dv = v - mean;
    __syncthreads();

    s = dv * dv;
    #pragma unroll
    for (int off = 16; off; off >>= 1) s += __shfl_xor_sync(0xffffffffu, s, off);
    if ((tid & 31) == 0) red[tid >> 5] = s;
    __syncthreads();
    float tot2 = 0.f;
    #pragma unroll
    for (int i = 0; i < 8; i++) tot2 += red[i];
    const float var = tot2 * (1.f / 256.f);

    o[idx] = dv * rsqrtf(var + 1e-5f);
}

// ---------------- masked mean over chars + scatter into padded ----------------
__global__ void pool_k(const float* __restrict__ wft, const int* __restrict__ toks,
                       const int* __restrict__ cid, const int* __restrict__ wpos,
                       float* __restrict__ pad) {
    const int w = blockIdx.x, d = threadIdx.x;
    __shared__ int val[LW];
    if (d < LW) val[d] = (toks[(size_t)w * LW + d] != 0);
    __syncthreads();
    float ssum = 0.f; int cnt = 0;
    #pragma unroll
    for (int j = 0; j < LW; j++) {
        if (val[j]) { ssum += wft[((size_t)w * LW + j) * D + d]; cnt++; }
    }
    pad[((size_t)cid[w] * MAXW + wpos[w]) * D + d] = ssum / (float)cnt;
}

// ---------------- final: zero pad rows, per-dim nonzero counts, pooled mean ----------------
__global__ void final_k(const float* __restrict__ nf, const float* __restrict__ pad,
                        float* __restrict__ out) {
    const int c = blockIdx.x, d = threadIdx.x;
    __shared__ int nz[MAXW];
    if (d < MAXW) nz[d] = 0;
    __syncthreads();
    #pragma unroll
    for (int w = 0; w < MAXW; w++) {
        if (pad[((size_t)c * MAXW + w) * D + d] != 0.f) atomicOr(&nz[w], 1);
    }
    __syncthreads();
    float ssum = 0.f; int cnt = 0;
    #pragma unroll
    for (int w = 0; w < MAXW; w++) {
        if (nz[w]) {
            float v = nf[((size_t)c * MAXW + w) * D + d];
            ssum += v;
            cnt += (v != 0.f);
        }
    }
    out[(size_t)c * D + d] = ssum / (float)cnt;
}

// ---------------- driver ----------------
extern "C" void kernel_launch(void* const* d_in, const int* in_sizes, int n_in,
                              void* d_out, int out_size) {
    const int* toks = (const int*)d_in[0];
    const int* cid  = (const int*)d_in[1];
    const int* wpos = (const int*)d_in[2];

    // weights start at the unique 128*256-element we_emb (scalars n_concepts /
    // n_names may or may not be materialized as size-1 tensors before it)
    int wi = 3;
    while (wi < n_in && in_sizes[wi] != 128 * 256) wi++;
    const float* we_emb = (const float*)d_in[wi + 0];
    const float* we_qkv = (const float*)d_in[wi + 1];
    const float* we_o   = (const float*)d_in[wi + 2];
    const float* we_ff1 = (const float*)d_in[wi + 3];
    const float* we_ff2 = (const float*)d_in[wi + 4];
    const float* ne_qkv = (const float*)d_in[wi + 5];
    const float* ne_o   = (const float*)d_in[wi + 6];
    const float* ne_ff1 = (const float*)d_in[wi + 7];
    const float* ne_ff2 = (const float*)d_in[wi + 8];
    float* out = (float*)d_out;

    float *x, *qkv, *attn, *t, *h, *ff, *pad;
    cudaGetSymbolAddress((void**)&x,    g_x);
    cudaGetSymbolAddress((void**)&qkv,  g_qkv);
    cudaGetSymbolAddress((void**)&attn, g_attn);
    cudaGetSymbolAddress((void**)&t,    g_t);
    cudaGetSymbolAddress((void**)&h,    g_h);
    cudaGetSymbolAddress((void**)&ff,   g_ff);
    cudaGetSymbolAddress((void**)&pad,  g_pad);

    cudaFuncSetAttribute(attn_k<LW, true>,
                         cudaFuncAttributeMaxDynamicSharedMemorySize, LW * 768 * 4);
    cudaFuncSetAttribute(attn_k<MAXW, false>,
                         cudaFuncAttributeMaxDynamicSharedMemorySize, MAXW * 768 * 4);

    // ===== block 1 (char transformer over 196608 tokens) =====
    embed_k<<<(M1 * D + 255) / 256, 256>>>(toks, we_emb, x, M1 * D);

    sgemm_k<false><<<dim3(3 * D / 128, M1 / 128), 256>>>(x, we_qkv, qkv, M1, 3 * D, D);
    attn_k<LW, true><<<NW, 256, LW * 768 * 4>>>(qkv, toks, attn);
    sgemm_k<false><<<dim3(D / 128, M1 / 128), 256>>>(attn, we_o, t, M1, D, D);
    addln_k<<<M1, 256>>>(x, t, h);
    sgemm_k<true ><<<dim3(DFF / 128, M1 / 128), 256>>>(h, we_ff1, ff, M1, DFF, D);
    sgemm_k<false><<<dim3(D / 128, M1 / 128), 256>>>(ff, we_ff2, t, M1, D, DFF);
    addln_k<<<M1, 256>>>(h, t, x);   // word_ft -> x

    // ===== pool chars -> words, scatter into padded [NC, MAXW, D] =====
    zero_k<<<(M2 * D + 255) / 256, 256>>>(pad, M2 * D);
    pool_k<<<NW, 256>>>(x, toks, cid, wpos, pad);

    // ===== block 2 (name transformer over 16384 tokens, no mask) =====
    sgemm_k<false><<<dim3(3 * D / 128, M2 / 128), 256>>>(pad, ne_qkv, qkv, M2, 3 * D, D);
    attn_k<MAXW, false><<<NC, 256, MAXW * 768 * 4>>>(qkv, nullptr, attn);
    sgemm_k<false><<<dim3(D / 128, M2 / 128), 256>>>(attn, ne_o, t, M2, D, D);
    addln_k<<<M2, 256>>>(pad, t, h);
    sgemm_k<true ><<<dim3(DFF / 128, M2 / 128), 256>>>(h, ne_ff1, ff, M2, DFF, D);
    sgemm_k<false><<<dim3(D / 128, M2 / 128), 256>>>(ff, ne_ff2, t, M2, D, DFF);
    addln_k<<<M2, 256>>>(h, t, attn); // name_ft -> attn

    // ===== pad-row zeroing + per-dim nonzero-count mean -> output =====
    final_k<<<NC, 256>>>(attn, pad, out);
}

// round 10
// speedup vs baseline: 3.1328x; 3.1328x over previous
#include <cuda_runtime.h>
#include <cuda_fp16.h>
#include <cstddef>
#include <cstdint>

// ---------------- problem constants ----------------
#define NW    8192
#define LW    24
#define D     256
#define NH    8
#define HD    32
#define DFF   1024
#define NC    1024
#define MAXW  16
#define M1    (NW*LW)       // 196608 tokens, block 1
#define M2    (NC*MAXW)     // 16384 tokens, block 2

// ---------------- scratch (device globals; no cudaMalloc allowed) ----------------
__device__ float  g_x   [(size_t)M1*D];
__device__ float  g_qkv [(size_t)M1*3*D];
__device__ float  g_t   [(size_t)M1*D];
__device__ float  g_h   [(size_t)M1*D];
__device__ float  g_nf  [(size_t)M1*D];     // name_ft (block2 final LN out)
__device__ __half g_xh  [(size_t)M1*D];
__device__ __half g_ah  [(size_t)M1*D];     // attention out (fp16, feeds o-proj)
__device__ __half g_hh  [(size_t)M1*D];     // post-attn LN (fp16, feeds ff1)
__device__ __half g_ffh [(size_t)M1*DFF];   // relu(ff1) (fp16, feeds ff2)
__device__ float  g_pad [(size_t)M2*D];
__device__ __half g_padh[(size_t)M2*D];

// transposed fp16 weights, [N][K] K-major
#define W_TOTAL 1572864
__device__ __half g_wh[W_TOTAL];
// element offsets: qkv1 0, o1 196608, ff1a 262144, ff2a 524288,
//                  qkv2 786432, o2 983040, ff1b 1048576, ff2b 1310720

// ---------------- weight transpose fp32 [K,N] -> fp16 [N][K] ----------------
__global__ void wconv_k(const float* __restrict__ W, __half* __restrict__ wh,
                        int K, int N) {
    int i = blockIdx.x * blockDim.x + threadIdx.x;
    if (i < K * N) {
        int n = i % N, k = i / N;
        wh[(size_t)n * K + k] = __float2half_rn(W[i]);
    }
}

// ---------------- embedding gather (fp32 + fp16 copies) ----------------
__global__ void embed_k(const int* __restrict__ toks, const float* __restrict__ emb,
                        float* __restrict__ x, __half* __restrict__ xh, int total) {
    int i = blockIdx.x * blockDim.x + threadIdx.x;
    if (i < total) {
        float v = emb[toks[i >> 8] * D + (i & 255)];
        x[i] = v;
        xh[i] = __float2half_rn(v);
    }
}

__global__ void zero2_k(float* __restrict__ p, __half* __restrict__ ph, int n) {
    int i = blockIdx.x * blockDim.x + threadIdx.x;
    if (i < n) { p[i] = 0.f; ph[i] = __float2half_rn(0.f); }
}

// ================= helpers =================
__device__ __forceinline__ uint32_t s2u(const void* p) {
    uint32_t a;
    asm("{ .reg .u64 t; cvta.to.shared.u64 t, %1; cvt.u32.u64 %0, t; }" : "=r"(a) : "l"(p));
    return a;
}
__device__ __forceinline__ void cpa16(uint32_t dst, const void* src) {
    asm volatile("cp.async.cg.shared.global [%0], [%1], 16;" :: "r"(dst), "l"(src));
}
__device__ __forceinline__ void ldsm4(uint32_t& r0, uint32_t& r1, uint32_t& r2,
                                      uint32_t& r3, uint32_t a) {
    asm volatile("ldmatrix.sync.aligned.m8n8.x4.shared.b16 {%0,%1,%2,%3}, [%4];"
                 : "=r"(r0), "=r"(r1), "=r"(r2), "=r"(r3) : "r"(a));
}
__device__ __forceinline__ void mma16816(float* c, const uint32_t* a,
                                         uint32_t b0, uint32_t b1) {
    asm volatile(
        "mma.sync.aligned.m16n8k16.row.col.f32.f16.f16.f32 "
        "{%0,%1,%2,%3}, {%4,%5,%6,%7}, {%8,%9}, {%0,%1,%2,%3};"
        : "+f"(c[0]), "+f"(c[1]), "+f"(c[2]), "+f"(c[3])
        : "r"(a[0]), "r"(a[1]), "r"(a[2]), "r"(a[3]), "r"(b0), "r"(b1));
}

// ---------------- fp16 tensor-core GEMM: C[M,N] = op(A[M,K] @ W[K,N]) ----------------
// A fp16 [M][K]; B fp16 [N][K] (W transposed). 128x128 CTA tile, BK=32,
// 4-stage cp.async pipeline, 8 warps x (64x32) via m16n8k16.
// MODE 0: fp32 C out. MODE 1: relu + fp16 C out.
#define ASTR 40                         // padded row stride (halves) -> 80B, conflict-free
#define SLOT (128*ASTR)                 // halves per slot per operand
#define HSME (4*SLOT*2*2)               // total dynamic smem bytes (4 stages, A+B)

template<int MODE>
__global__ void __launch_bounds__(256, 2) hgemm_k(const __half* __restrict__ A,
                                                  const __half* __restrict__ B,
                                                  float* __restrict__ Cf,
                                                  __half* __restrict__ Ch,
                                                  int M, int N, int K) {
    extern __shared__ __half sm[];
    const int tid = threadIdx.x, lane = tid & 31, wid = tid >> 5;
    const int bm = blockIdx.y << 7, bn = blockIdx.x << 7;
    const int wm = (wid & 1) << 6, wn = (wid >> 1) << 5;

    __half* Bsl = sm + 4 * SLOT;
    const uint32_t aBase = s2u(sm), bBase = s2u(Bsl);

    // loader: thread -> row tid>>1, chunks (tid&1)*2 + {0,1} (16B each)
    const int lr = tid >> 1;
    const int lc = (tid & 1) * 16;       // element offset of first chunk (8 halves each)
    const __half* Ag = A + (size_t)(bm + lr) * K + lc;
    const __half* Bg = B + (size_t)(bn + lr) * K + lc;
    const uint32_t aDst = aBase + (uint32_t)(lr * ASTR + lc) * 2;
    const uint32_t bDst = bBase + (uint32_t)(lr * ASTR + lc) * 2;
    const uint32_t slotB = SLOT * 2;     // bytes per slot

    float acc[4][4][4];
    #pragma unroll
    for (int i = 0; i < 4; i++)
        #pragma unroll
        for (int j = 0; j < 4; j++)
            #pragma unroll
            for (int q = 0; q < 4; q++) acc[i][j][q] = 0.f;

    const int nk = K >> 5;
    #pragma unroll
    for (int s = 0; s < 3; s++) {
        cpa16(aDst + s * slotB,      Ag + s * 32);
        cpa16(aDst + s * slotB + 16, Ag + s * 32 + 8);
        cpa16(bDst + s * slotB,      Bg + s * 32);
        cpa16(bDst + s * slotB + 16, Bg + s * 32 + 8);
        asm volatile("cp.async.commit_group;");
    }

    const int krow = lane & 15, kh = (lane >> 4) * 8;
    for (int j = 0; j < nk; j++) {
        asm volatile("cp.async.wait_group 2;");
        __syncthreads();
        const int p = j + 3;
        if (p < nk) {
            const int sl = p & 3;
            cpa16(aDst + sl * slotB,      Ag + p * 32);
            cpa16(aDst + sl * slotB + 16, Ag + p * 32 + 8);
            cpa16(bDst + sl * slotB,      Bg + p * 32);
            cpa16(bDst + sl * slotB + 16, Bg + p * 32 + 8);
        }
        asm volatile("cp.async.commit_group;");

        const uint32_t aS = aBase + (uint32_t)(j & 3) * slotB;
        const uint32_t bS = bBase + (uint32_t)(j & 3) * slotB;
        #pragma unroll
        for (int k16 = 0; k16 < 2; k16++) {
            uint32_t a[4][4], b[2][4];
            #pragma unroll
            for (int mf = 0; mf < 4; mf++)
                ldsm4(a[mf][0], a[mf][1], a[mf][2], a[mf][3],
                      aS + (uint32_t)((wm + mf * 16 + krow) * ASTR + k16 * 16 + kh) * 2);
            #pragma unroll
            for (int bf = 0; bf < 2; bf++)
                ldsm4(b[bf][0], b[bf][1], b[bf][2], b[bf][3],
                      bS + (uint32_t)((wn + bf * 16 + krow) * ASTR + k16 * 16 + kh) * 2);
            #pragma unroll
            for (int mf = 0; mf < 4; mf++)
                #pragma unroll
                for (int nf = 0; nf < 4; nf++)
                    mma16816(acc[mf][nf], a[mf],
                             b[nf >> 1][nf & 1], b[nf >> 1][2 + (nf & 1)]);
        }
    }

    // epilogue
    const int r0 = bm + wm + (lane >> 2);
    const int c0 = bn + wn + (lane & 3) * 2;
    #pragma unroll
    for (int mf = 0; mf < 4; mf++) {
        #pragma unroll
        for (int nf = 0; nf < 4; nf++) {
            const int r = r0 + mf * 16, c = c0 + nf * 8;
            float* ac = acc[mf][nf];
            if (MODE == 0) {
                *(float2*)(Cf + (size_t)r * N + c)       = make_float2(ac[0], ac[1]);
                *(float2*)(Cf + (size_t)(r + 8) * N + c) = make_float2(ac[2], ac[3]);
            } else {
                __half2 h0 = __floats2half2_rn(fmaxf(ac[0], 0.f), fmaxf(ac[1], 0.f));
                __half2 h1 = __floats2half2_rn(fmaxf(ac[2], 0.f), fmaxf(ac[3], 0.f));
                *(__half2*)(Ch + (size_t)r * N + c)       = h0;
                *(__half2*)(Ch + (size_t)(r + 8) * N + c) = h1;
            }
        }
    }
}

// ---------------- attention: one block per word, one warp per head ----------------
template<int LT, bool MASKED>
__global__ void __launch_bounds__(256) attn_k(const float* __restrict__ qkv,
                                              const int* __restrict__ toks,
                                              __half* __restrict__ out) {
    extern __shared__ float s[];
    __shared__ int smask[32];
    const int w = blockIdx.x, tid = threadIdx.x;

    const float4* base = (const float4*)(qkv + (size_t)w * LT * 768);
    float4* s4 = (float4*)s;
    for (int i = tid; i < LT * 192; i += 256) s4[i] = base[i];
    if (MASKED) {
        if (tid < LT) smask[tid] = (toks[(size_t)w * LT + tid] == 0);
    }
    __syncthreads();

    const int h = tid >> 5, lane = tid & 31;
    if (lane < LT) {
        float q[HD];
        const float* qp = s + lane * 768 + h * HD;
        #pragma unroll
        for (int d = 0; d < HD; d++) q[d] = qp[d];

        float p[LT];
        float mx = -1e30f;
        #pragma unroll
        for (int j = 0; j < LT; j++) {
            const float* kp = s + j * 768 + 256 + h * HD;
            float a = 0.f;
            #pragma unroll
            for (int d = 0; d < HD; d++) a += q[d] * kp[d];
            a *= 0.17677669529663687f;
            if (MASKED && smask[j]) a = -1e9f;
            p[j] = a;
            mx = fmaxf(mx, a);
        }
        float sum = 0.f;
        #pragma unroll
        for (int j = 0; j < LT; j++) { p[j] = expf(p[j] - mx); sum += p[j]; }
        const float inv = 1.f / sum;

        __half* op = out + ((size_t)w * LT + lane) * D + h * HD;
        #pragma unroll
        for (int d = 0; d < HD; d++) {
            float a = 0.f;
            #pragma unroll
            for (int j = 0; j < LT; j++) a += p[j] * s[j * 768 + 512 + h * HD + d];
            op[d] = __float2half_rn(a * inv);
        }
    }
}

// ---------------- residual add + LayerNorm (fp32 out, optional fp16 copy) ----------------
template<bool HOUT>
__global__ void __launch_bounds__(256) addln_k(const float* __restrict__ a,
                                               const float* __restrict__ b,
                                               float* __restrict__ o,
                                               __half* __restrict__ oh) {
    const int row = blockIdx.x, tid = threadIdx.x;
    const size_t idx = (size_t)row * D + tid;
    const float v = a[idx] + b[idx];

    __shared__ float red[8];
    float s = v;
    #pragma unroll
    for (int off = 16; off; off >>= 1) s += __shfl_xor_sync(0xffffffffu, s, off);
    if ((tid & 31) == 0) red[tid >> 5] = s;
    __syncthreads();
    float tot = 0.f;
    #pragma unroll
    for (int i = 0; i < 8; i++) tot += red[i];
    const float mean = tot * (1.f / 256.f);
    const float dv = v - mean;
    __syncthreads();

    s = dv * dv;
    #pragma unroll
    for (int off = 16; off; off >>= 1) s += __shfl_xor_sync(0xffffffffu, s, off);
    if ((tid & 31) == 0) red[tid >> 5] = s;
    __syncthreads();
    float tot2 = 0.f;
    #pragma unroll
    for (int i = 0; i < 8; i++) tot2 += red[i];
    const float var = tot2 * (1.f / 256.f);

    const float r = dv * rsqrtf(var + 1e-5f);
    o[idx] = r;
    if (HOUT) oh[idx] = __float2half_rn(r);
}

// ---------------- masked mean over chars + scatter into padded ----------------
__global__ void pool_k(const float* __restrict__ wft, const int* __restrict__ toks,
                       const int* __restrict__ cid, const int* __restrict__ wpos,
                       float* __restrict__ pad, __half* __restrict__ padh) {
    const int w = blockIdx.x, d = threadIdx.x;
    __shared__ int val[LW];
    if (d < LW) val[d] = (toks[(size_t)w * LW + d] != 0);
    __syncthreads();
    float ssum = 0.f; int cnt = 0;
    #pragma unroll
    for (int j = 0; j < LW; j++) {
        if (val[j]) { ssum += wft[((size_t)w * LW + j) * D + d]; cnt++; }
    }
    const float r = ssum / (float)cnt;
    const size_t oi = ((size_t)cid[w] * MAXW + wpos[w]) * D + d;
    pad[oi]  = r;
    padh[oi] = __float2half_rn(r);
}

// ---------------- final pooling ----------------
__global__ void final_k(const float* __restrict__ nf, const float* __restrict__ pad,
                        float* __restrict__ out) {
    const int c = blockIdx.x, d = threadIdx.x;
    __shared__ int nz[MAXW];
    if (d < MAXW) nz[d] = 0;
    __syncthreads();
    #pragma unroll
    for (int w = 0; w < MAXW; w++) {
        if (pad[((size_t)c * MAXW + w) * D + d] != 0.f) atomicOr(&nz[w], 1);
    }
    __syncthreads();
    float ssum = 0.f; int cnt = 0;
    #pragma unroll
    for (int w = 0; w < MAXW; w++) {
        if (nz[w]) {
            float v = nf[((size_t)c * MAXW + w) * D + d];
            ssum += v;
            cnt += (v != 0.f);
        }
    }
    out[(size_t)c * D + d] = ssum / (float)cnt;
}

// ---------------- driver ----------------
extern "C" void kernel_launch(void* const* d_in, const int* in_sizes, int n_in,
                              void* d_out, int out_size) {
    const int* toks = (const int*)d_in[0];
    const int* cid  = (const int*)d_in[1];
    const int* wpos = (const int*)d_in[2];

    int wi = 3;
    while (wi < n_in && in_sizes[wi] != 128 * 256) wi++;
    const float* we_emb = (const float*)d_in[wi + 0];
    const float* we_qkv = (const float*)d_in[wi + 1];
    const float* we_o   = (const float*)d_in[wi + 2];
    const float* we_ff1 = (const float*)d_in[wi + 3];
    const float* we_ff2 = (const float*)d_in[wi + 4];
    const float* ne_qkv = (const float*)d_in[wi + 5];
    const float* ne_o   = (const float*)d_in[wi + 6];
    const float* ne_ff1 = (const float*)d_in[wi + 7];
    const float* ne_ff2 = (const float*)d_in[wi + 8];
    float* out = (float*)d_out;

    float *x, *qkv, *t, *h, *nf, *pad;
    __half *xh, *ah, *hh, *ffh, *padh, *wh;
    cudaGetSymbolAddress((void**)&x,    g_x);
    cudaGetSymbolAddress((void**)&qkv,  g_qkv);
    cudaGetSymbolAddress((void**)&t,    g_t);
    cudaGetSymbolAddress((void**)&h,    g_h);
    cudaGetSymbolAddress((void**)&nf,   g_nf);
    cudaGetSymbolAddress((void**)&pad,  g_pad);
    cudaGetSymbolAddress((void**)&xh,   g_xh);
    cudaGetSymbolAddress((void**)&ah,   g_ah);
    cudaGetSymbolAddress((void**)&hh,   g_hh);
    cudaGetSymbolAddress((void**)&ffh,  g_ffh);
    cudaGetSymbolAddress((void**)&padh, g_padh);
    cudaGetSymbolAddress((void**)&wh,   g_wh);

    cudaFuncSetAttribute(hgemm_k<0>, cudaFuncAttributeMaxDynamicSharedMemorySize, HSME);
    cudaFuncSetAttribute(hgemm_k<1>, cudaFuncAttributeMaxDynamicSharedMemorySize, HSME);
    cudaFuncSetAttribute(attn_k<LW, true>,
                         cudaFuncAttributeMaxDynamicSharedMemorySize, LW * 768 * 4);
    cudaFuncSetAttribute(attn_k<MAXW, false>,
                         cudaFuncAttributeMaxDynamicSharedMemorySize, MAXW * 768 * 4);

    // ===== weight transpose -> fp16 [N][K] =====
    auto WC = [&](const float* W, size_t off, int K, int N) {
        wconv_k<<<(K * N + 255) / 256, 256>>>(W, wh + off, K, N);
    };
    WC(we_qkv, 0,       D,   3 * D);
    WC(we_o,   196608,  D,   D);
    WC(we_ff1, 262144,  D,   DFF);
    WC(we_ff2, 524288,  DFF, D);
    WC(ne_qkv, 786432,  D,   3 * D);
    WC(ne_o,   983040,  D,   D);
    WC(ne_ff1, 1048576, D,   DFF);
    WC(ne_ff2, 1310720, DFF, D);

    // ===== block 1 (char transformer, 196608 tokens) =====
    embed_k<<<(M1 * D + 255) / 256, 256>>>(toks, we_emb, x, xh, M1 * D);

    hgemm_k<0><<<dim3(6, M1 / 128), 256, HSME>>>(xh, wh, qkv, nullptr, M1, 3 * D, D);
    attn_k<LW, true><<<NW, 256, LW * 768 * 4>>>(qkv, toks, ah);
    hgemm_k<0><<<dim3(2, M1 / 128), 256, HSME>>>(ah, wh + 196608, t, nullptr, M1, D, D);
    addln_k<true><<<M1, 256>>>(x, t, h, hh);
    hgemm_k<1><<<dim3(8, M1 / 128), 256, HSME>>>(hh, wh + 262144, nullptr, ffh, M1, DFF, D);
    hgemm_k<0><<<dim3(2, M1 / 128), 256, HSME>>>(ffh, wh + 524288, t, nullptr, M1, D, DFF);
    addln_k<false><<<M1, 256>>>(h, t, x, nullptr);   // word_ft -> x

    // ===== pool chars -> words, scatter into padded [NC, MAXW, D] =====
    zero2_k<<<(M2 * D + 255) / 256, 256>>>(pad, padh, M2 * D);
    pool_k<<<NW, 256>>>(x, toks, cid, wpos, pad, padh);

    // ===== block 2 (name transformer, 16384 tokens) =====
    hgemm_k<0><<<dim3(6, M2 / 128), 256, HSME>>>(padh, wh + 786432, qkv, nullptr, M2, 3 * D, D);
    attn_k<MAXW, false><<<NC, 256, MAXW * 768 * 4>>>(qkv, nullptr, ah);
    hgemm_k<0><<<dim3(2, M2 / 128), 256, HSME>>>(ah, wh + 983040, t, nullptr, M2, D, D);
    addln_k<true><<<M2, 256>>>(pad, t, h, hh);
    hgemm_k<1><<<dim3(8, M2 / 128), 256, HSME>>>(hh, wh + 1048576, nullptr, ffh, M2, DFF, D);
    hgemm_k<0><<<dim3(2, M2 / 128), 256, HSME>>>(ffh, wh + 1310720, t, nullptr, M2, D, DFF);
    addln_k<false><<<M2, 256>>>(h, t, nf, nullptr);  // name_ft

    // ===== final pooling -> output =====
    final_k<<<NC, 256>>>(nf, pad, out);
}

// round 12
// speedup vs baseline: 3.2578x; 1.0399x over previous
#include <cuda_runtime.h>
#include <cuda_fp16.h>
#include <cstddef>
#include <cstdint>

// ---------------- problem constants ----------------
#define NW    8192
#define LW    24
#define D     256
#define NH    8
#define HD    32
#define DFF   1024
#define NC    1024
#define MAXW  16
#define M1    (NW*LW)       // 196608 tokens, block 1
#define M2    (NC*MAXW)     // 16384 tokens, block 2

// ---------------- scratch (device globals; no cudaMalloc allowed) ----------------
__device__ float  g_x   [(size_t)M1*D];
__device__ float  g_qkv [(size_t)M1*3*D];   // fp16 view used for qkv (aliased)
__device__ float  g_t   [(size_t)M1*D];
__device__ float  g_h   [(size_t)M1*D];
__device__ float  g_nf  [(size_t)M1*D];     // name_ft (block2 final LN out)
__device__ __half g_xh  [(size_t)M1*D];
__device__ __half g_ah  [(size_t)M1*D];     // attention out (fp16, feeds o-proj)
__device__ __half g_hh  [(size_t)M1*D];     // post-attn LN (fp16, feeds ff1)
__device__ __half g_ffh [(size_t)M1*DFF];   // relu(ff1) (fp16, feeds ff2)
__device__ float  g_pad [(size_t)M2*D];
__device__ __half g_padh[(size_t)M2*D];

// transposed fp16 weights, [N][K] K-major
#define W_TOTAL 1572864
__device__ __half g_wh[W_TOTAL];
// element offsets: qkv1 0, o1 196608, ff1a 262144, ff2a 524288,
//                  qkv2 786432, o2 983040, ff1b 1048576, ff2b 1310720

// ---------------- weight transpose fp32 [K,N] -> fp16 [N][K] ----------------
__global__ void wconv_k(const float* __restrict__ W, __half* __restrict__ wh,
                        int K, int N) {
    int i = blockIdx.x * blockDim.x + threadIdx.x;
    if (i < K * N) {
        int n = i % N, k = i / N;
        wh[(size_t)n * K + k] = __float2half_rn(W[i]);
    }
}

// ---------------- embedding gather (fp32 + fp16 copies) ----------------
__global__ void embed_k(const int* __restrict__ toks, const float* __restrict__ emb,
                        float* __restrict__ x, __half* __restrict__ xh, int total) {
    int i = blockIdx.x * blockDim.x + threadIdx.x;
    if (i < total) {
        float v = emb[toks[i >> 8] * D + (i & 255)];
        x[i] = v;
        xh[i] = __float2half_rn(v);
    }
}

__global__ void zero2_k(float* __restrict__ p, __half* __restrict__ ph, int n) {
    int i = blockIdx.x * blockDim.x + threadIdx.x;
    if (i < n) { p[i] = 0.f; ph[i] = __float2half_rn(0.f); }
}

// ================= helpers =================
__device__ __forceinline__ uint32_t s2u(const void* p) {
    uint32_t a;
    asm("{ .reg .u64 t; cvta.to.shared.u64 t, %1; cvt.u32.u64 %0, t; }" : "=r"(a) : "l"(p));
    return a;
}
__device__ __forceinline__ void cpa16(uint32_t dst, const void* src) {
    asm volatile("cp.async.cg.shared.global [%0], [%1], 16;" :: "r"(dst), "l"(src));
}
__device__ __forceinline__ void ldsm4(uint32_t& r0, uint32_t& r1, uint32_t& r2,
                                      uint32_t& r3, uint32_t a) {
    asm volatile("ldmatrix.sync.aligned.m8n8.x4.shared.b16 {%0,%1,%2,%3}, [%4];"
                 : "=r"(r0), "=r"(r1), "=r"(r2), "=r"(r3) : "r"(a));
}
__device__ __forceinline__ void mma16816(float* c, const uint32_t* a,
                                         uint32_t b0, uint32_t b1) {
    asm volatile(
        "mma.sync.aligned.m16n8k16.row.col.f32.f16.f16.f32 "
        "{%0,%1,%2,%3}, {%4,%5,%6,%7}, {%8,%9}, {%0,%1,%2,%3};"
        : "+f"(c[0]), "+f"(c[1]), "+f"(c[2]), "+f"(c[3])
        : "r"(a[0]), "r"(a[1]), "r"(a[2]), "r"(a[3]), "r"(b0), "r"(b1));
}

// ---------------- fp16 tensor-core GEMM: C[M,N] = op(A[M,K] @ W[K,N]) ----------------
// A fp16 [M][K]; B fp16 [N][K] (W transposed). 128x128 CTA tile, BK=32,
// 4-stage cp.async pipeline, 8 warps x (64x32) via m16n8k16.
// All 12 ldmatrix for the BK=32 chunk are issued before the MMA block; the
// next stage's cp.async is issued between loads and MMAs.
// MODE 0: fp32 C out. MODE 1: relu + fp16 C out. MODE 2: fp16 C out.
#define ASTR 40                         // padded row stride (halves) -> 80B, conflict-free
#define SLOT (128*ASTR)                 // halves per slot per operand
#define HSME (4*SLOT*2*2)               // total dynamic smem bytes (4 stages, A+B)

template<int MODE>
__global__ void __launch_bounds__(256, 2) hgemm_k(const __half* __restrict__ A,
                                                  const __half* __restrict__ B,
                                                  float* __restrict__ Cf,
                                                  __half* __restrict__ Ch,
                                                  int M, int N, int K) {
    extern __shared__ __half sm[];
    const int tid = threadIdx.x, lane = tid & 31, wid = tid >> 5;
    const int bm = blockIdx.y << 7, bn = blockIdx.x << 7;
    const int wm = (wid & 1) << 6, wn = (wid >> 1) << 5;

    __half* Bsl = sm + 4 * SLOT;
    const uint32_t aBase = s2u(sm), bBase = s2u(Bsl);

    const int lr = tid >> 1;
    const int lc = (tid & 1) * 16;
    const __half* Ag = A + (size_t)(bm + lr) * K + lc;
    const __half* Bg = B + (size_t)(bn + lr) * K + lc;
    const uint32_t aDst = aBase + (uint32_t)(lr * ASTR + lc) * 2;
    const uint32_t bDst = bBase + (uint32_t)(lr * ASTR + lc) * 2;
    const uint32_t slotB = SLOT * 2;

    float acc[4][4][4];
    #pragma unroll
    for (int i = 0; i < 4; i++)
        #pragma unroll
        for (int j = 0; j < 4; j++)
            #pragma unroll
            for (int q = 0; q < 4; q++) acc[i][j][q] = 0.f;

    const int nk = K >> 5;
    #pragma unroll
    for (int s = 0; s < 3; s++) {
        cpa16(aDst + s * slotB,      Ag + s * 32);
        cpa16(aDst + s * slotB + 16, Ag + s * 32 + 8);
        cpa16(bDst + s * slotB,      Bg + s * 32);
        cpa16(bDst + s * slotB + 16, Bg + s * 32 + 8);
        asm volatile("cp.async.commit_group;");
    }

    const int krow = lane & 15, kh = (lane >> 4) * 8;
    const uint32_t aW = (uint32_t)((wm + krow) * ASTR + kh) * 2;
    const uint32_t bW = (uint32_t)((wn + krow) * ASTR + kh) * 2;

    for (int j = 0; j < nk; j++) {
        asm volatile("cp.async.wait_group 2;");
        __syncthreads();

        const uint32_t aS = aBase + (uint32_t)(j & 3) * slotB + aW;
        const uint32_t bS = bBase + (uint32_t)(j & 3) * slotB + bW;

        // ---- all fragment loads for this BK=32 chunk ----
        uint32_t a[2][4][4], b[2][2][4];
        #pragma unroll
        for (int k16 = 0; k16 < 2; k16++) {
            #pragma unroll
            for (int mf = 0; mf < 4; mf++)
                ldsm4(a[k16][mf][0], a[k16][mf][1], a[k16][mf][2], a[k16][mf][3],
                      aS + (uint32_t)(mf * 16 * ASTR + k16 * 16) * 2);
            #pragma unroll
            for (int bf = 0; bf < 2; bf++)
                ldsm4(b[k16][bf][0], b[k16][bf][1], b[k16][bf][2], b[k16][bf][3],
                      bS + (uint32_t)(bf * 16 * ASTR + k16 * 16) * 2);
        }

        // ---- prefetch next stage while LDSMs are in flight ----
        const int p = j + 3;
        if (p < nk) {
            const int sl = p & 3;
            cpa16(aDst + sl * slotB,      Ag + p * 32);
            cpa16(aDst + sl * slotB + 16, Ag + p * 32 + 8);
            cpa16(bDst + sl * slotB,      Bg + p * 32);
            cpa16(bDst + sl * slotB + 16, Bg + p * 32 + 8);
        }
        asm volatile("cp.async.commit_group;");

        // ---- 64 MMAs, dependency-free chain ----
        #pragma unroll
        for (int k16 = 0; k16 < 2; k16++)
            #pragma unroll
            for (int mf = 0; mf < 4; mf++)
                #pragma unroll
                for (int nf = 0; nf < 4; nf++)
                    mma16816(acc[mf][nf], a[k16][mf],
                             b[k16][nf >> 1][nf & 1], b[k16][nf >> 1][2 + (nf & 1)]);
    }

    // epilogue
    const int r0 = bm + wm + (lane >> 2);
    const int c0 = bn + wn + (lane & 3) * 2;
    #pragma unroll
    for (int mf = 0; mf < 4; mf++) {
        #pragma unroll
        for (int nf = 0; nf < 4; nf++) {
            const int r = r0 + mf * 16, c = c0 + nf * 8;
            float* ac = acc[mf][nf];
            if (MODE == 0) {
                *(float2*)(Cf + (size_t)r * N + c)       = make_float2(ac[0], ac[1]);
                *(float2*)(Cf + (size_t)(r + 8) * N + c) = make_float2(ac[2], ac[3]);
            } else if (MODE == 1) {
                __half2 h0 = __floats2half2_rn(fmaxf(ac[0], 0.f), fmaxf(ac[1], 0.f));
                __half2 h1 = __floats2half2_rn(fmaxf(ac[2], 0.f), fmaxf(ac[3], 0.f));
                *(__half2*)(Ch + (size_t)r * N + c)       = h0;
                *(__half2*)(Ch + (size_t)(r + 8) * N + c) = h1;
            } else {
                __half2 h0 = __floats2half2_rn(ac[0], ac[1]);
                __half2 h1 = __floats2half2_rn(ac[2], ac[3]);
                *(__half2*)(Ch + (size_t)r * N + c)       = h0;
                *(__half2*)(Ch + (size_t)(r + 8) * N + c) = h1;
            }
        }
    }
}

// ---------------- attention: fp16 qkv in, fp32 smem + fp32 math ----------------
template<int LT, bool MASKED>
__global__ void __launch_bounds__(256) attn_k(const __half* __restrict__ qkv,
                                              const int* __restrict__ toks,
                                              __half* __restrict__ out) {
    extern __shared__ float s[];   // LT * 768 floats
    __shared__ int smask[32];
    const int w = blockIdx.x, tid = threadIdx.x;

    // load fp16, convert once to fp32 smem
    const uint4* base = (const uint4*)(qkv + (size_t)w * LT * 768);
    for (int i = tid; i < LT * 96; i += 256) {
        uint4 v = base[i];
        const __half2* hp = (const __half2*)&v;
        float* dst = s + i * 8;
        float2 f0 = __half22float2(hp[0]);
        float2 f1 = __half22float2(hp[1]);
        float2 f2 = __half22float2(hp[2]);
        float2 f3 = __half22float2(hp[3]);
        *(float4*)dst       = make_float4(f0.x, f0.y, f1.x, f1.y);
        *(float4*)(dst + 4) = make_float4(f2.x, f2.y, f3.x, f3.y);
    }
    if (MASKED) {
        if (tid < LT) smask[tid] = (toks[(size_t)w * LT + tid] == 0);
    }
    __syncthreads();

    const int h = tid >> 5, lane = tid & 31;
    if (lane < LT) {
        float q[HD];
        const float* qp = s + lane * 768 + h * HD;
        #pragma unroll
        for (int d = 0; d < HD; d++) q[d] = qp[d];

        float p[LT];
        float mx = -1e30f;
        #pragma unroll
        for (int j = 0; j < LT; j++) {
            const float* kp = s + j * 768 + 256 + h * HD;
            float a = 0.f;
            #pragma unroll
            for (int d = 0; d < HD; d++) a += q[d] * kp[d];
            a *= 0.17677669529663687f;
            if (MASKED && smask[j]) a = -1e9f;
            p[j] = a;
            mx = fmaxf(mx, a);
        }
        float sum = 0.f;
        #pragma unroll
        for (int j = 0; j < LT; j++) { p[j] = expf(p[j] - mx); sum += p[j]; }
        const float inv = 1.f / sum;

        __half* op = out + ((size_t)w * LT + lane) * D + h * HD;
        #pragma unroll
        for (int d = 0; d < HD; d++) {
            float a = 0.f;
            #pragma unroll
            for (int j = 0; j < LT; j++) a += p[j] * s[j * 768 + 512 + h * HD + d];
            op[d] = __float2half_rn(a * inv);
        }
    }
}

// ---------------- residual add + LayerNorm (fp32 out, optional fp16 copy) ----------------
template<bool HOUT>
__global__ void __launch_bounds__(256) addln_k(const float* __restrict__ a,
                                               const float* __restrict__ b,
                                               float* __restrict__ o,
                                               __half* __restrict__ oh) {
    const int row = blockIdx.x, tid = threadIdx.x;
    const size_t idx = (size_t)row * D + tid;
    const float v = a[idx] + b[idx];

    __shared__ float red[8];
    float s = v;
    #pragma unroll
    for (int off = 16; off; off >>= 1) s += __shfl_xor_sync(0xffffffffu, s, off);
    if ((tid & 31) == 0) red[tid >> 5] = s;
    __syncthreads();
    float tot = 0.f;
    #pragma unroll
    for (int i = 0; i < 8; i++) tot += red[i];
    const float mean = tot * (1.f / 256.f);
    const float dv = v - mean;
    __syncthreads();

    s = dv * dv;
    #pragma unroll
    for (int off = 16; off; off >>= 1) s += __shfl_xor_sync(0xffffffffu, s, off);
    if ((tid & 31) == 0) red[tid >> 5] = s;
    __syncthreads();
    float tot2 = 0.f;
    #pragma unroll
    for (int i = 0; i < 8; i++) tot2 += red[i];
    const float var = tot2 * (1.f / 256.f);

    const float r = dv * rsqrtf(var + 1e-5f);
    o[idx] = r;
    if (HOUT) oh[idx] = __float2half_rn(r);
}

// ---------------- masked mean over chars + scatter into padded ----------------
__global__ void pool_k(const float* __restrict__ wft, const int* __restrict__ toks,
                       const int* __restrict__ cid, const int* __restrict__ wpos,
                       float* __restrict__ pad, __half* __restrict__ padh) {
    const int w = blockIdx.x, d = threadIdx.x;
    __shared__ int val[LW];
    if (d < LW) val[d] = (toks[(size_t)w * LW + d] != 0);
    __syncthreads();
    float ssum = 0.f; int cnt = 0;
    #pragma unroll
    for (int j = 0; j < LW; j++) {
        if (val[j]) { ssum += wft[((size_t)w * LW + j) * D + d]; cnt++; }
    }
    const float r = ssum / (float)cnt;
    const size_t oi = ((size_t)cid[w] * MAXW + wpos[w]) * D + d;
    pad[oi]  = r;
    padh[oi] = __float2half_rn(r);
}

// ---------------- final pooling ----------------
__global__ void final_k(const float* __restrict__ nf, const float* __restrict__ pad,
                        float* __restrict__ out) {
    const int c = blockIdx.x, d = threadIdx.x;
    __shared__ int nz[MAXW];
    if (d < MAXW) nz[d] = 0;
    __syncthreads();
    #pragma unroll
    for (int w = 0; w < MAXW; w++) {
        if (pad[((size_t)c * MAXW + w) * D + d] != 0.f) atomicOr(&nz[w], 1);
    }
    __syncthreads();
    float ssum = 0.f; int cnt = 0;
    #pragma unroll
    for (int w = 0; w < MAXW; w++) {
        if (nz[w]) {
            float v = nf[((size_t)c * MAXW + w) * D + d];
            ssum += v;
            cnt += (v != 0.f);
        }
    }
    out[(size_t)c * D + d] = ssum / (float)cnt;
}

// ---------------- driver ----------------
extern "C" void kernel_launch(void* const* d_in, const int* in_sizes, int n_in,
                              void* d_out, int out_size) {
    const int* toks = (const int*)d_in[0];
    const int* cid  = (const int*)d_in[1];
    const int* wpos = (const int*)d_in[2];

    int wi = 3;
    while (wi < n_in && in_sizes[wi] != 128 * 256) wi++;
    const float* we_emb = (const float*)d_in[wi + 0];
    const float* we_qkv = (const float*)d_in[wi + 1];
    const float* we_o   = (const float*)d_in[wi + 2];
    const float* we_ff1 = (const float*)d_in[wi + 3];
    const float* we_ff2 = (const float*)d_in[wi + 4];
    const float* ne_qkv = (const float*)d_in[wi + 5];
    const float* ne_o   = (const float*)d_in[wi + 6];
    const float* ne_ff1 = (const float*)d_in[wi + 7];
    const float* ne_ff2 = (const float*)d_in[wi + 8];
    float* out = (float*)d_out;

    float *x, *qkvf, *t, *h, *nf, *pad;
    __half *xh, *ah, *hh, *ffh, *padh, *wh;
    cudaGetSymbolAddress((void**)&x,    g_x);
    cudaGetSymbolAddress((void**)&qkvf, g_qkv);
    cudaGetSymbolAddress((void**)&t,    g_t);
    cudaGetSymbolAddress((void**)&h,    g_h);
    cudaGetSymbolAddress((void**)&nf,   g_nf);
    cudaGetSymbolAddress((void**)&pad,  g_pad);
    cudaGetSymbolAddress((void**)&xh,   g_xh);
    cudaGetSymbolAddress((void**)&ah,   g_ah);
    cudaGetSymbolAddress((void**)&hh,   g_hh);
    cudaGetSymbolAddress((void**)&ffh,  g_ffh);
    cudaGetSymbolAddress((void**)&padh, g_padh);
    cudaGetSymbolAddress((void**)&wh,   g_wh);
    __half* qkvh = (__half*)qkvf;   // alias: qkv kept in fp16

    cudaFuncSetAttribute(hgemm_k<0>, cudaFuncAttributeMaxDynamicSharedMemorySize, HSME);
    cudaFuncSetAttribute(hgemm_k<1>, cudaFuncAttributeMaxDynamicSharedMemorySize, HSME);
    cudaFuncSetAttribute(hgemm_k<2>, cudaFuncAttributeMaxDynamicSharedMemorySize, HSME);
    cudaFuncSetAttribute(attn_k<LW, true>,
                         cudaFuncAttributeMaxDynamicSharedMemorySize, LW * 768 * 4);
    cudaFuncSetAttribute(attn_k<MAXW, false>,
                         cudaFuncAttributeMaxDynamicSharedMemorySize, MAXW * 768 * 4);

    // ===== weight transpose -> fp16 [N][K] =====
    auto WC = [&](const float* W, size_t off, int K, int N) {
        wconv_k<<<(K * N + 255) / 256, 256>>>(W, wh + off, K, N);
    };
    WC(we_qkv, 0,       D,   3 * D);
    WC(we_o,   196608,  D,   D);
    WC(we_ff1, 262144,  D,   DFF);
    WC(we_ff2, 524288,  DFF, D);
    WC(ne_qkv, 786432,  D,   3 * D);
    WC(ne_o,   983040,  D,   D);
    WC(ne_ff1, 1048576, D,   DFF);
    WC(ne_ff2, 1310720, DFF, D);

    // ===== block 1 (char transformer, 196608 tokens) =====
    embed_k<<<(M1 * D + 255) / 256, 256>>>(toks, we_emb, x, xh, M1 * D);

    hgemm_k<2><<<dim3(6, M1 / 128), 256, HSME>>>(xh, wh, nullptr, qkvh, M1, 3 * D, D);
    attn_k<LW, true><<<NW, 256, LW * 768 * 4>>>(qkvh, toks, ah);
    hgemm_k<0><<<dim3(2, M1 / 128), 256, HSME>>>(ah, wh + 196608, t, nullptr, M1, D, D);
    addln_k<true><<<M1, 256>>>(x, t, h, hh);
    hgemm_k<1><<<dim3(8, M1 / 128), 256, HSME>>>(hh, wh + 262144, nullptr, ffh, M1, DFF, D);
    hgemm_k<0><<<dim3(2, M1 / 128), 256, HSME>>>(ffh, wh + 524288, t, nullptr, M1, D, DFF);
    addln_k<false><<<M1, 256>>>(h, t, x, nullptr);   // word_ft -> x

    // ===== pool chars -> words, scatter into padded [NC, MAXW, D] =====
    zero2_k<<<(M2 * D + 255) / 256, 256>>>(pad, padh, M2 * D);
    pool_k<<<NW, 256>>>(x, toks, cid, wpos, pad, padh);

    // ===== block 2 (name transformer, 16384 tokens) =====
    hgemm_k<2><<<dim3(6, M2 / 128), 256, HSME>>>(padh, wh + 786432, nullptr, qkvh, M2, 3 * D, D);
    attn_k<MAXW, false><<<NC, 256, MAXW * 768 * 4>>>(qkvh, nullptr, ah);
    hgemm_k<0><<<dim3(2, M2 / 128), 256, HSME>>>(ah, wh + 983040, t, nullptr, M2, D, D);
    addln_k<true><<<M2, 256>>>(pad, t, h, hh);
    hgemm_k<1><<<dim3(8, M2 / 128), 256, HSME>>>(hh, wh + 1048576, nullptr, ffh, M2, DFF, D);
    hgemm_k<0><<<dim3(2, M2 / 128), 256, HSME>>>(ffh, wh + 1310720, t, nullptr, M2, D, DFF);
    addln_k<false><<<M2, 256>>>(h, t, nf, nullptr);  // name_ft

    // ===== final pooling -> output =====
    final_k<<<NC, 256>>>(nf, pad, out);
}

// round 13
// speedup vs baseline: 3.7754x; 1.1589x over previous
#include <cuda_runtime.h>
#include <cuda_fp16.h>
#include <cstddef>
#include <cstdint>

// ---------------- problem constants ----------------
#define NW    8192
#define LW    24
#define D     256
#define NH    8
#define HD    32
#define DFF   1024
#define NC    1024
#define MAXW  16
#define M1    (NW*LW)       // 196608 tokens, block 1
#define M2    (NC*MAXW)     // 16384 tokens, block 2

// ---------------- scratch (device globals; no cudaMalloc allowed) ----------------
__device__ float  g_x   [(size_t)M1*D];
__device__ float  g_qkv [(size_t)M1*3*D];   // fp16 view used for qkv (aliased)
__device__ float  g_h   [(size_t)M1*D];
__device__ float  g_nf  [(size_t)M1*D];     // name_ft (block2 final LN out)
__device__ __half g_xh  [(size_t)M1*D];
__device__ __half g_ah  [(size_t)M1*D];     // attention out (fp16, feeds o-proj)
__device__ __half g_hh  [(size_t)M1*D];     // post-attn LN (fp16, feeds ff1)
__device__ __half g_ffh [(size_t)M1*DFF];   // relu(ff1) (fp16, feeds ff2)
__device__ float  g_pad [(size_t)M2*D];
__device__ __half g_padh[(size_t)M2*D];

// transposed fp16 weights, [N][K] K-major
#define W_TOTAL 1572864
__device__ __half g_wh[W_TOTAL];
// element offsets: qkv1 0, o1 196608, ff1a 262144, ff2a 524288,
//                  qkv2 786432, o2 983040, ff1b 1048576, ff2b 1310720

// ---------------- weight transpose fp32 [K,N] -> fp16 [N][K] ----------------
__global__ void wconv_k(const float* __restrict__ W, __half* __restrict__ wh,
                        int K, int N) {
    int i = blockIdx.x * blockDim.x + threadIdx.x;
    if (i < K * N) {
        int n = i % N, k = i / N;
        wh[(size_t)n * K + k] = __float2half_rn(W[i]);
    }
}

// ---------------- embedding gather (fp32 + fp16 copies) ----------------
__global__ void embed_k(const int* __restrict__ toks, const float* __restrict__ emb,
                        float* __restrict__ x, __half* __restrict__ xh, int total) {
    int i = blockIdx.x * blockDim.x + threadIdx.x;
    if (i < total) {
        float v = emb[toks[i >> 8] * D + (i & 255)];
        x[i] = v;
        xh[i] = __float2half_rn(v);
    }
}

__global__ void zero2_k(float* __restrict__ p, __half* __restrict__ ph, int n) {
    int i = blockIdx.x * blockDim.x + threadIdx.x;
    if (i < n) { p[i] = 0.f; ph[i] = __float2half_rn(0.f); }
}

// ================= helpers =================
__device__ __forceinline__ uint32_t s2u(const void* p) {
    uint32_t a;
    asm("{ .reg .u64 t; cvta.to.shared.u64 t, %1; cvt.u32.u64 %0, t; }" : "=r"(a) : "l"(p));
    return a;
}
__device__ __forceinline__ void cpa16(uint32_t dst, const void* src) {
    asm volatile("cp.async.cg.shared.global [%0], [%1], 16;" :: "r"(dst), "l"(src));
}
__device__ __forceinline__ void ldsm4(uint32_t& r0, uint32_t& r1, uint32_t& r2,
                                      uint32_t& r3, uint32_t a) {
    asm volatile("ldmatrix.sync.aligned.m8n8.x4.shared.b16 {%0,%1,%2,%3}, [%4];"
                 : "=r"(r0), "=r"(r1), "=r"(r2), "=r"(r3) : "r"(a));
}
__device__ __forceinline__ void mma16816(float* c, const uint32_t* a,
                                         uint32_t b0, uint32_t b1) {
    asm volatile(
        "mma.sync.aligned.m16n8k16.row.col.f32.f16.f16.f32 "
        "{%0,%1,%2,%3}, {%4,%5,%6,%7}, {%8,%9}, {%0,%1,%2,%3};"
        : "+f"(c[0]), "+f"(c[1]), "+f"(c[2]), "+f"(c[3])
        : "r"(a[0]), "r"(a[1]), "r"(a[2]), "r"(a[3]), "r"(b0), "r"(b1));
}

// ---------------- fp16 tensor-core GEMM: C[M,N] = op(A[M,K] @ W[K,N]) ----------------
// A fp16 [M][K]; B fp16 [N][K] (W transposed). 128x128 CTA tile, BK=32,
// 4-stage cp.async pipeline, 8 warps x (64x32) via m16n8k16.
// MODE 1: relu + fp16 C out. MODE 2: fp16 C out.
#define ASTR 40                         // padded row stride (halves) -> 80B, conflict-free
#define SLOT (128*ASTR)                 // halves per slot per operand
#define HSME (4*SLOT*2*2)               // total dynamic smem bytes (4 stages, A+B)

template<int MODE>
__global__ void __launch_bounds__(256, 2) hgemm_k(const __half* __restrict__ A,
                                                  const __half* __restrict__ B,
                                                  __half* __restrict__ Ch,
                                                  int M, int N, int K) {
    extern __shared__ __half sm[];
    const int tid = threadIdx.x, lane = tid & 31, wid = tid >> 5;
    const int bm = blockIdx.y << 7, bn = blockIdx.x << 7;
    const int wm = (wid & 1) << 6, wn = (wid >> 1) << 5;

    __half* Bsl = sm + 4 * SLOT;
    const uint32_t aBase = s2u(sm), bBase = s2u(Bsl);

    const int lr = tid >> 1;
    const int lc = (tid & 1) * 16;
    const __half* Ag = A + (size_t)(bm + lr) * K + lc;
    const __half* Bg = B + (size_t)(bn + lr) * K + lc;
    const uint32_t aDst = aBase + (uint32_t)(lr * ASTR + lc) * 2;
    const uint32_t bDst = bBase + (uint32_t)(lr * ASTR + lc) * 2;
    const uint32_t slotB = SLOT * 2;

    float acc[4][4][4];
    #pragma unroll
    for (int i = 0; i < 4; i++)
        #pragma unroll
        for (int j = 0; j < 4; j++)
            #pragma unroll
            for (int q = 0; q < 4; q++) acc[i][j][q] = 0.f;

    const int nk = K >> 5;
    #pragma unroll
    for (int s = 0; s < 3; s++) {
        cpa16(aDst + s * slotB,      Ag + s * 32);
        cpa16(aDst + s * slotB + 16, Ag + s * 32 + 8);
        cpa16(bDst + s * slotB,      Bg + s * 32);
        cpa16(bDst + s * slotB + 16, Bg + s * 32 + 8);
        asm volatile("cp.async.commit_group;");
    }

    const int krow = lane & 15, kh = (lane >> 4) * 8;
    const uint32_t aW = (uint32_t)((wm + krow) * ASTR + kh) * 2;
    const uint32_t bW = (uint32_t)((wn + krow) * ASTR + kh) * 2;

    for (int j = 0; j < nk; j++) {
        asm volatile("cp.async.wait_group 2;");
        __syncthreads();

        const uint32_t aS = aBase + (uint32_t)(j & 3) * slotB + aW;
        const uint32_t bS = bBase + (uint32_t)(j & 3) * slotB + bW;

        uint32_t a[2][4][4], b[2][2][4];
        #pragma unroll
        for (int k16 = 0; k16 < 2; k16++) {
            #pragma unroll
            for (int mf = 0; mf < 4; mf++)
                ldsm4(a[k16][mf][0], a[k16][mf][1], a[k16][mf][2], a[k16][mf][3],
                      aS + (uint32_t)(mf * 16 * ASTR + k16 * 16) * 2);
            #pragma unroll
            for (int bf = 0; bf < 2; bf++)
                ldsm4(b[k16][bf][0], b[k16][bf][1], b[k16][bf][2], b[k16][bf][3],
                      bS + (uint32_t)(bf * 16 * ASTR + k16 * 16) * 2);
        }

        const int p = j + 3;
        if (p < nk) {
            const int sl = p & 3;
            cpa16(aDst + sl * slotB,      Ag + p * 32);
            cpa16(aDst + sl * slotB + 16, Ag + p * 32 + 8);
            cpa16(bDst + sl * slotB,      Bg + p * 32);
            cpa16(bDst + sl * slotB + 16, Bg + p * 32 + 8);
        }
        asm volatile("cp.async.commit_group;");

        #pragma unroll
        for (int k16 = 0; k16 < 2; k16++)
            #pragma unroll
            for (int mf = 0; mf < 4; mf++)
                #pragma unroll
                for (int nf = 0; nf < 4; nf++)
                    mma16816(acc[mf][nf], a[k16][mf],
                             b[k16][nf >> 1][nf & 1], b[k16][nf >> 1][2 + (nf & 1)]);
    }

    const int r0 = bm + wm + (lane >> 2);
    const int c0 = bn + wn + (lane & 3) * 2;
    #pragma unroll
    for (int mf = 0; mf < 4; mf++) {
        #pragma unroll
        for (int nf = 0; nf < 4; nf++) {
            const int r = r0 + mf * 16, c = c0 + nf * 8;
            float* ac = acc[mf][nf];
            __half2 h0, h1;
            if (MODE == 1) {
                h0 = __floats2half2_rn(fmaxf(ac[0], 0.f), fmaxf(ac[1], 0.f));
                h1 = __floats2half2_rn(fmaxf(ac[2], 0.f), fmaxf(ac[3], 0.f));
            } else {
                h0 = __floats2half2_rn(ac[0], ac[1]);
                h1 = __floats2half2_rn(ac[2], ac[3]);
            }
            *(__half2*)(Ch + (size_t)r * N + c)       = h0;
            *(__half2*)(Ch + (size_t)(r + 8) * N + c) = h1;
        }
    }
}

// ---------------- fused GEMM + residual + LayerNorm (N fixed = 256) ----------------
// C = A[M,K] @ W[K,256]; out = LN(res + C), fp32 (+ optional fp16 copy).
// 64x256 CTA tile so each CTA owns full rows; 8 warps = 2(m) x 4(n), 32x64 each.
// 3-stage cp.async pipeline, BK=32.
#define LN_ABYTES (64*ASTR*2)           // 5120
#define LN_BBYTES (256*ASTR*2)          // 20480
#define LN_STAGE  (LN_ABYTES+LN_BBYTES) // 25600
#define LN_SMEM   (3*LN_STAGE)          // 76800 (epilogue staging 64x260 f32 = 66560 fits)

template<bool HOUT>
__global__ void __launch_bounds__(256, 2)
hgemm_ln_k(const __half* __restrict__ A, const __half* __restrict__ B,
           const float* __restrict__ res, float* __restrict__ Of,
           __half* __restrict__ Oh, int M, int K) {
    extern __shared__ __half sm[];
    const int tid = threadIdx.x, lane = tid & 31, wid = tid >> 5;
    const int bm = blockIdx.x << 6;
    const uint32_t base = s2u(sm);
    const int wm = (wid >> 2) << 5, wn = (wid & 3) << 6;

    // loaders: A 64 rows x 4 chunks(16B) = 256 -> 1/thread; B 256x4 = 1024 -> 4/thread
    const int ar = tid >> 2, ac = (tid & 3) * 8;
    const __half* Ag = A + (size_t)(bm + ar) * K + ac;
    const uint32_t aDst = base + (uint32_t)(ar * ASTR + ac) * 2;

    float acc[2][8][4];
    #pragma unroll
    for (int i = 0; i < 2; i++)
        #pragma unroll
        for (int j = 0; j < 8; j++)
            #pragma unroll
            for (int q = 0; q < 4; q++) acc[i][j][q] = 0.f;

    const int nk = K >> 5;

    auto fill = [&](int st, int k0) {
        const uint32_t so = (uint32_t)st * LN_STAGE;
        cpa16(aDst + so, Ag + k0);
        #pragma unroll
        for (int j2 = 0; j2 < 4; j2++) {
            int idx = j2 * 256 + tid;
            int br = idx >> 2, bc = (idx & 3) * 8;
            cpa16(base + so + LN_ABYTES + (uint32_t)(br * ASTR + bc) * 2,
                  B + (size_t)br * K + k0 + bc);
        }
        asm volatile("cp.async.commit_group;");
    };

    fill(0, 0);
    fill(1, 32);

    const int krow = lane & 15, kh = (lane >> 4) * 8;
    const uint32_t aW = (uint32_t)((wm + krow) * ASTR + kh) * 2;
    const uint32_t bW = (uint32_t)((wn + krow) * ASTR + kh) * 2 + LN_ABYTES;

    int slot = 0;
    for (int j = 0; j < nk; j++) {
        asm volatile("cp.async.wait_group 1;");
        __syncthreads();
        const uint32_t so = (uint32_t)slot * LN_STAGE;
        const uint32_t aS = base + so + aW;
        const uint32_t bS = base + so + bW;

        // k16 = 0
        uint32_t a0[2][4], b0[4][4];
        #pragma unroll
        for (int mf = 0; mf < 2; mf++)
            ldsm4(a0[mf][0], a0[mf][1], a0[mf][2], a0[mf][3],
                  aS + (uint32_t)(mf * 16 * ASTR) * 2);
        #pragma unroll
        for (int bf = 0; bf < 4; bf++)
            ldsm4(b0[bf][0], b0[bf][1], b0[bf][2], b0[bf][3],
                  bS + (uint32_t)(bf * 16 * ASTR) * 2);

        const int p = j + 2;
        if (p < nk) fill((slot + 2) % 3, p * 32);
        else asm volatile("cp.async.commit_group;");

        #pragma unroll
        for (int mf = 0; mf < 2; mf++)
            #pragma unroll
            for (int nf = 0; nf < 8; nf++)
                mma16816(acc[mf][nf], a0[mf],
                         b0[nf >> 1][nf & 1], b0[nf >> 1][2 + (nf & 1)]);

        // k16 = 1
        uint32_t a1[2][4], b1[4][4];
        #pragma unroll
        for (int mf = 0; mf < 2; mf++)
            ldsm4(a1[mf][0], a1[mf][1], a1[mf][2], a1[mf][3],
                  aS + (uint32_t)(mf * 16 * ASTR + 16) * 2);
        #pragma unroll
        for (int bf = 0; bf < 4; bf++)
            ldsm4(b1[bf][0], b1[bf][1], b1[bf][2], b1[bf][3],
                  bS + (uint32_t)(bf * 16 * ASTR + 16) * 2);
        #pragma unroll
        for (int mf = 0; mf < 2; mf++)
            #pragma unroll
            for (int nf = 0; nf < 8; nf++)
                mma16816(acc[mf][nf], a1[mf],
                         b1[nf >> 1][nf & 1], b1[nf >> 1][2 + (nf & 1)]);

        slot++; if (slot == 3) slot = 0;
    }

    __syncthreads();   // all smem reads done; reuse for staging

    // stage accumulators: 64 rows x 256 cols, row stride 260 floats
    float* stg = (float*)sm;
    const int r0 = wm + (lane >> 2), c0 = wn + (lane & 3) * 2;
    #pragma unroll
    for (int mf = 0; mf < 2; mf++) {
        #pragma unroll
        for (int nf = 0; nf < 8; nf++) {
            const int r = r0 + mf * 16, c = c0 + nf * 8;
            float* ac = acc[mf][nf];
            stg[r * 260 + c]           = ac[0];
            stg[r * 260 + c + 1]       = ac[1];
            stg[(r + 8) * 260 + c]     = ac[2];
            stg[(r + 8) * 260 + c + 1] = ac[3];
        }
    }
    __syncthreads();

    // LayerNorm: each warp handles 8 rows
    #pragma unroll
    for (int rr = 0; rr < 8; rr++) {
        const int r = wid * 8 + rr;
        const size_t gr = (size_t)(bm + r) * 256;
        float v[8];
        float sum = 0.f;
        #pragma unroll
        for (int q = 0; q < 8; q++) {
            v[q] = stg[r * 260 + lane + q * 32] + res[gr + lane + q * 32];
            sum += v[q];
        }
        #pragma unroll
        for (int off = 16; off; off >>= 1) sum += __shfl_xor_sync(0xffffffffu, sum, off);
        const float mean = sum * (1.f / 256.f);
        float sq = 0.f;
        #pragma unroll
        for (int q = 0; q < 8; q++) { float d = v[q] - mean; sq += d * d; }
        #pragma unroll
        for (int off = 16; off; off >>= 1) sq += __shfl_xor_sync(0xffffffffu, sq, off);
        const float rs = rsqrtf(sq * (1.f / 256.f) + 1e-5f);
        #pragma unroll
        for (int q = 0; q < 8; q++) {
            const float o = (v[q] - mean) * rs;
            Of[gr + lane + q * 32] = o;
            if (HOUT) Oh[gr + lane + q * 32] = __float2half_rn(o);
        }
    }
}

// ---------------- attention: fp16 qkv in, fp32 smem + fp32 math ----------------
template<int LT, bool MASKED>
__global__ void __launch_bounds__(256) attn_k(const __half* __restrict__ qkv,
                                              const int* __restrict__ toks,
                                              __half* __restrict__ out) {
    extern __shared__ float s[];
    __shared__ int smask[32];
    const int w = blockIdx.x, tid = threadIdx.x;

    const uint4* base = (const uint4*)(qkv + (size_t)w * LT * 768);
    for (int i = tid; i < LT * 96; i += 256) {
        uint4 v = base[i];
        const __half2* hp = (const __half2*)&v;
        float* dst = s + i * 8;
        float2 f0 = __half22float2(hp[0]);
        float2 f1 = __half22float2(hp[1]);
        float2 f2 = __half22float2(hp[2]);
        float2 f3 = __half22float2(hp[3]);
        *(float4*)dst       = make_float4(f0.x, f0.y, f1.x, f1.y);
        *(float4*)(dst + 4) = make_float4(f2.x, f2.y, f3.x, f3.y);
    }
    if (MASKED) {
        if (tid < LT) smask[tid] = (toks[(size_t)w * LT + tid] == 0);
    }
    __syncthreads();

    const int h = tid >> 5, lane = tid & 31;
    if (lane < LT) {
        float q[HD];
        const float* qp = s + lane * 768 + h * HD;
        #pragma unroll
        for (int d = 0; d < HD; d++) q[d] = qp[d];

        float p[LT];
        float mx = -1e30f;
        #pragma unroll
        for (int j = 0; j < LT; j++) {
            const float* kp = s + j * 768 + 256 + h * HD;
            float a = 0.f;
            #pragma unroll
            for (int d = 0; d < HD; d++) a += q[d] * kp[d];
            a *= 0.17677669529663687f;
            if (MASKED && smask[j]) a = -1e9f;
            p[j] = a;
            mx = fmaxf(mx, a);
        }
        float sum = 0.f;
        #pragma unroll
        for (int j = 0; j < LT; j++) { p[j] = expf(p[j] - mx); sum += p[j]; }
        const float inv = 1.f / sum;

        __half* op = out + ((size_t)w * LT + lane) * D + h * HD;
        #pragma unroll
        for (int d = 0; d < HD; d++) {
            float a = 0.f;
            #pragma unroll
            for (int j = 0; j < LT; j++) a += p[j] * s[j * 768 + 512 + h * HD + d];
            op[d] = __float2half_rn(a * inv);
        }
    }
}

// ---------------- masked mean over chars + scatter into padded ----------------
__global__ void pool_k(const float* __restrict__ wft, const int* __restrict__ toks,
                       const int* __restrict__ cid, const int* __restrict__ wpos,
                       float* __restrict__ pad, __half* __restrict__ padh) {
    const int w = blockIdx.x, d = threadIdx.x;
    __shared__ int val[LW];
    if (d < LW) val[d] = (toks[(size_t)w * LW + d] != 0);
    __syncthreads();
    float ssum = 0.f; int cnt = 0;
    #pragma unroll
    for (int j = 0; j < LW; j++) {
        if (val[j]) { ssum += wft[((size_t)w * LW + j) * D + d]; cnt++; }
    }
    const float r = ssum / (float)cnt;
    const size_t oi = ((size_t)cid[w] * MAXW + wpos[w]) * D + d;
    pad[oi]  = r;
    padh[oi] = __float2half_rn(r);
}

// ---------------- final pooling ----------------
__global__ void final_k(const float* __restrict__ nf, const float* __restrict__ pad,
                        float* __restrict__ out) {
    const int c = blockIdx.x, d = threadIdx.x;
    __shared__ int nz[MAXW];
    if (d < MAXW) nz[d] = 0;
    __syncthreads();
    #pragma unroll
    for (int w = 0; w < MAXW; w++) {
        if (pad[((size_t)c * MAXW + w) * D + d] != 0.f) atomicOr(&nz[w], 1);
    }
    __syncthreads();
    float ssum = 0.f; int cnt = 0;
    #pragma unroll
    for (int w = 0; w < MAXW; w++) {
        if (nz[w]) {
            float v = nf[((size_t)c * MAXW + w) * D + d];
            ssum += v;
            cnt += (v != 0.f);
        }
    }
    out[(size_t)c * D + d] = ssum / (float)cnt;
}

// ---------------- driver ----------------
extern "C" void kernel_launch(void* const* d_in, const int* in_sizes, int n_in,
                              void* d_out, int out_size) {
    const int* toks = (const int*)d_in[0];
    const int* cid  = (const int*)d_in[1];
    const int* wpos = (const int*)d_in[2];

    int wi = 3;
    while (wi < n_in && in_sizes[wi] != 128 * 256) wi++;
    const float* we_emb = (const float*)d_in[wi + 0];
    const float* we_qkv = (const float*)d_in[wi + 1];
    const float* we_o   = (const float*)d_in[wi + 2];
    const float* we_ff1 = (const float*)d_in[wi + 3];
    const float* we_ff2 = (const float*)d_in[wi + 4];
    const float* ne_qkv = (const float*)d_in[wi + 5];
    const float* ne_o   = (const float*)d_in[wi + 6];
    const float* ne_ff1 = (const float*)d_in[wi + 7];
    const float* ne_ff2 = (const float*)d_in[wi + 8];
    float* out = (float*)d_out;

    float *x, *qkvf, *h, *nf, *pad;
    __half *xh, *ah, *hh, *ffh, *padh, *wh;
    cudaGetSymbolAddress((void**)&x,    g_x);
    cudaGetSymbolAddress((void**)&qkvf, g_qkv);
    cudaGetSymbolAddress((void**)&h,    g_h);
    cudaGetSymbolAddress((void**)&nf,   g_nf);
    cudaGetSymbolAddress((void**)&pad,  g_pad);
    cudaGetSymbolAddress((void**)&xh,   g_xh);
    cudaGetSymbolAddress((void**)&ah,   g_ah);
    cudaGetSymbolAddress((void**)&hh,   g_hh);
    cudaGetSymbolAddress((void**)&ffh,  g_ffh);
    cudaGetSymbolAddress((void**)&padh, g_padh);
    cudaGetSymbolAddress((void**)&wh,   g_wh);
    __half* qkvh = (__half*)qkvf;   // alias: qkv kept in fp16

    cudaFuncSetAttribute(hgemm_k<1>, cudaFuncAttributeMaxDynamicSharedMemorySize, HSME);
    cudaFuncSetAttribute(hgemm_k<2>, cudaFuncAttributeMaxDynamicSharedMemorySize, HSME);
    cudaFuncSetAttribute(hgemm_ln_k<true>,
                         cudaFuncAttributeMaxDynamicSharedMemorySize, LN_SMEM);
    cudaFuncSetAttribute(hgemm_ln_k<false>,
                         cudaFuncAttributeMaxDynamicSharedMemorySize, LN_SMEM);
    cudaFuncSetAttribute(attn_k<LW, true>,
                         cudaFuncAttributeMaxDynamicSharedMemorySize, LW * 768 * 4);
    cudaFuncSetAttribute(attn_k<MAXW, false>,
                         cudaFuncAttributeMaxDynamicSharedMemorySize, MAXW * 768 * 4);

    auto WC = [&](const float* W, size_t off, int K, int N) {
        wconv_k<<<(K * N + 255) / 256, 256>>>(W, wh + off, K, N);
    };

    // ===== block 1 (char transformer, 196608 tokens) =====
    // launch order interleaves wconv with first use so ncu -s 5 hits hgemm_ln_k
    WC(we_qkv, 0, D, 3 * D);                                                   // 0
    embed_k<<<(M1 * D + 255) / 256, 256>>>(toks, we_emb, x, xh, M1 * D);       // 1
    hgemm_k<2><<<dim3(6, M1 / 128), 256, HSME>>>(xh, wh, qkvh, M1, 3 * D, D);  // 2
    attn_k<LW, true><<<NW, 256, LW * 768 * 4>>>(qkvh, toks, ah);               // 3
    WC(we_o, 196608, D, D);                                                    // 4
    hgemm_ln_k<true><<<M1 / 64, 256, LN_SMEM>>>(ah, wh + 196608, x, h, hh, M1, D);   // 5 (profiled)
    WC(we_ff1, 262144, D, DFF);                                                // 6
    hgemm_k<1><<<dim3(8, M1 / 128), 256, HSME>>>(hh, wh + 262144, ffh, M1, DFF, D);  // 7
    WC(we_ff2, 524288, DFF, D);                                                // 8
    hgemm_ln_k<false><<<M1 / 64, 256, LN_SMEM>>>(ffh, wh + 524288, h, x, nullptr, M1, DFF); // 9: word_ft -> x

    // ===== pool chars -> words, scatter into padded [NC, MAXW, D] =====
    zero2_k<<<(M2 * D + 255) / 256, 256>>>(pad, padh, M2 * D);
    pool_k<<<NW, 256>>>(x, toks, cid, wpos, pad, padh);

    // ===== block 2 (name transformer, 16384 tokens) =====
    WC(ne_qkv, 786432, D, 3 * D);
    hgemm_k<2><<<dim3(6, M2 / 128), 256, HSME>>>(padh, wh + 786432, qkvh, M2, 3 * D, D);
    attn_k<MAXW, false><<<NC, 256, MAXW * 768 * 4>>>(qkvh, nullptr, ah);
    WC(ne_o, 983040, D, D);
    hgemm_ln_k<true><<<M2 / 64, 256, LN_SMEM>>>(ah, wh + 983040, pad, h, hh, M2, D);
    WC(ne_ff1, 1048576, D, DFF);
    hgemm_k<1><<<dim3(8, M2 / 128), 256, HSME>>>(hh, wh + 1048576, ffh, M2, DFF, D);
    WC(ne_ff2, 1310720, DFF, D);
    hgemm_ln_k<false><<<M2 / 64, 256, LN_SMEM>>>(ffh, wh + 1310720, h, nf, nullptr, M2, DFF);

    // ===== final pooling -> output =====
    final_k<<<NC, 256>>>(nf, pad, out);
}

// round 14
// speedup vs baseline: 4.4546x; 1.1799x over previous
#include <cuda_runtime.h>
#include <cuda_fp16.h>
#include <cstddef>
#include <cstdint>

// ---------------- problem constants ----------------
#define NW    8192
#define LW    24
#define D     256
#define NH    8
#define HD    32
#define DFF   1024
#define NC    1024
#define MAXW  16
#define M1    (NW*LW)       // 196608 tokens, block 1
#define M2    (NC*MAXW)     // 16384 tokens, block 2

// ---------------- scratch (device globals; no cudaMalloc allowed) ----------------
__device__ float  g_x   [(size_t)M1*D];
__device__ float  g_qkv [(size_t)M1*3*D];   // fp16 view used for qkv (aliased)
__device__ float  g_h   [(size_t)M1*D];
__device__ float  g_nf  [(size_t)M1*D];     // name_ft (block2 final LN out)
__device__ __half g_xh  [(size_t)M1*D];
__device__ __half g_ah  [(size_t)M1*D];     // attention out (fp16, feeds o-proj)
__device__ __half g_hh  [(size_t)M1*D];     // post-attn LN (fp16, feeds ff1)
__device__ __half g_ffh [(size_t)M1*DFF];   // relu(ff1) (fp16, feeds ff2)
__device__ float  g_pad [(size_t)M2*D];
__device__ __half g_padh[(size_t)M2*D];

// transposed fp16 weights, [N][K] K-major
#define W_TOTAL 1572864
__device__ __half g_wh[W_TOTAL];
// element offsets: qkv1 0, o1 196608, ff1a 262144, ff2a 524288,
//                  qkv2 786432, o2 983040, ff1b 1048576, ff2b 1310720

// ---------------- weight transpose fp32 [K,N] -> fp16 [N][K] ----------------
__global__ void wconv_k(const float* __restrict__ W, __half* __restrict__ wh,
                        int K, int N) {
    int i = blockIdx.x * blockDim.x + threadIdx.x;
    if (i < K * N) {
        int n = i % N, k = i / N;
        wh[(size_t)n * K + k] = __float2half_rn(W[i]);
    }
}

// ---------------- embedding gather (fp32 + fp16 copies) ----------------
__global__ void embed_k(const int* __restrict__ toks, const float* __restrict__ emb,
                        float* __restrict__ x, __half* __restrict__ xh, int total) {
    int i = blockIdx.x * blockDim.x + threadIdx.x;
    if (i < total) {
        float v = emb[toks[i >> 8] * D + (i & 255)];
        x[i] = v;
        xh[i] = __float2half_rn(v);
    }
}

__global__ void zero2_k(float* __restrict__ p, __half* __restrict__ ph, int n) {
    int i = blockIdx.x * blockDim.x + threadIdx.x;
    if (i < n) { p[i] = 0.f; ph[i] = __float2half_rn(0.f); }
}

// ================= helpers =================
__device__ __forceinline__ uint32_t s2u(const void* p) {
    uint32_t a;
    asm("{ .reg .u64 t; cvta.to.shared.u64 t, %1; cvt.u32.u64 %0, t; }" : "=r"(a) : "l"(p));
    return a;
}
__device__ __forceinline__ void cpa16(uint32_t dst, const void* src) {
    asm volatile("cp.async.cg.shared.global [%0], [%1], 16;" :: "r"(dst), "l"(src));
}
__device__ __forceinline__ void ldsm4(uint32_t& r0, uint32_t& r1, uint32_t& r2,
                                      uint32_t& r3, uint32_t a) {
    asm volatile("ldmatrix.sync.aligned.m8n8.x4.shared.b16 {%0,%1,%2,%3}, [%4];"
                 : "=r"(r0), "=r"(r1), "=r"(r2), "=r"(r3) : "r"(a));
}
__device__ __forceinline__ void mma16816(float* c, const uint32_t* a,
                                         uint32_t b0, uint32_t b1) {
    asm volatile(
        "mma.sync.aligned.m16n8k16.row.col.f32.f16.f16.f32 "
        "{%0,%1,%2,%3}, {%4,%5,%6,%7}, {%8,%9}, {%0,%1,%2,%3};"
        : "+f"(c[0]), "+f"(c[1]), "+f"(c[2]), "+f"(c[3])
        : "r"(a[0]), "r"(a[1]), "r"(a[2]), "r"(a[3]), "r"(b0), "r"(b1));
}

// ---------------- fp16 tensor-core GEMM: C[M,N] = op(A[M,K] @ W[K,N]) ----------------
#define ASTR 40
#define SLOT (128*ASTR)
#define HSME (4*SLOT*2*2)

template<int MODE>   // 1: relu+fp16 out, 2: fp16 out
__global__ void __launch_bounds__(256, 2) hgemm_k(const __half* __restrict__ A,
                                                  const __half* __restrict__ B,
                                                  __half* __restrict__ Ch,
                                                  int M, int N, int K) {
    extern __shared__ __half sm[];
    const int tid = threadIdx.x, lane = tid & 31, wid = tid >> 5;
    const int bm = blockIdx.y << 7, bn = blockIdx.x << 7;
    const int wm = (wid & 1) << 6, wn = (wid >> 1) << 5;

    __half* Bsl = sm + 4 * SLOT;
    const uint32_t aBase = s2u(sm), bBase = s2u(Bsl);

    const int lr = tid >> 1;
    const int lc = (tid & 1) * 16;
    const __half* Ag = A + (size_t)(bm + lr) * K + lc;
    const __half* Bg = B + (size_t)(bn + lr) * K + lc;
    const uint32_t aDst = aBase + (uint32_t)(lr * ASTR + lc) * 2;
    const uint32_t bDst = bBase + (uint32_t)(lr * ASTR + lc) * 2;
    const uint32_t slotB = SLOT * 2;

    float acc[4][4][4];
    #pragma unroll
    for (int i = 0; i < 4; i++)
        #pragma unroll
        for (int j = 0; j < 4; j++)
            #pragma unroll
            for (int q = 0; q < 4; q++) acc[i][j][q] = 0.f;

    const int nk = K >> 5;
    #pragma unroll
    for (int s = 0; s < 3; s++) {
        cpa16(aDst + s * slotB,      Ag + s * 32);
        cpa16(aDst + s * slotB + 16, Ag + s * 32 + 8);
        cpa16(bDst + s * slotB,      Bg + s * 32);
        cpa16(bDst + s * slotB + 16, Bg + s * 32 + 8);
        asm volatile("cp.async.commit_group;");
    }

    const int krow = lane & 15, kh = (lane >> 4) * 8;
    const uint32_t aW = (uint32_t)((wm + krow) * ASTR + kh) * 2;
    const uint32_t bW = (uint32_t)((wn + krow) * ASTR + kh) * 2;

    for (int j = 0; j < nk; j++) {
        asm volatile("cp.async.wait_group 2;");
        __syncthreads();

        const uint32_t aS = aBase + (uint32_t)(j & 3) * slotB + aW;
        const uint32_t bS = bBase + (uint32_t)(j & 3) * slotB + bW;

        uint32_t a[2][4][4], b[2][2][4];
        #pragma unroll
        for (int k16 = 0; k16 < 2; k16++) {
            #pragma unroll
            for (int mf = 0; mf < 4; mf++)
                ldsm4(a[k16][mf][0], a[k16][mf][1], a[k16][mf][2], a[k16][mf][3],
                      aS + (uint32_t)(mf * 16 * ASTR + k16 * 16) * 2);
            #pragma unroll
            for (int bf = 0; bf < 2; bf++)
                ldsm4(b[k16][bf][0], b[k16][bf][1], b[k16][bf][2], b[k16][bf][3],
                      bS + (uint32_t)(bf * 16 * ASTR + k16 * 16) * 2);
        }

        const int p = j + 3;
        if (p < nk) {
            const int sl = p & 3;
            cpa16(aDst + sl * slotB,      Ag + p * 32);
            cpa16(aDst + sl * slotB + 16, Ag + p * 32 + 8);
            cpa16(bDst + sl * slotB,      Bg + p * 32);
            cpa16(bDst + sl * slotB + 16, Bg + p * 32 + 8);
        }
        asm volatile("cp.async.commit_group;");

        #pragma unroll
        for (int k16 = 0; k16 < 2; k16++)
            #pragma unroll
            for (int mf = 0; mf < 4; mf++)
                #pragma unroll
                for (int nf = 0; nf < 4; nf++)
                    mma16816(acc[mf][nf], a[k16][mf],
                             b[k16][nf >> 1][nf & 1], b[k16][nf >> 1][2 + (nf & 1)]);
    }

    const int r0 = bm + wm + (lane >> 2);
    const int c0 = bn + wn + (lane & 3) * 2;
    #pragma unroll
    for (int mf = 0; mf < 4; mf++) {
        #pragma unroll
        for (int nf = 0; nf < 4; nf++) {
            const int r = r0 + mf * 16, c = c0 + nf * 8;
            float* ac = acc[mf][nf];
            __half2 h0, h1;
            if (MODE == 1) {
                h0 = __floats2half2_rn(fmaxf(ac[0], 0.f), fmaxf(ac[1], 0.f));
                h1 = __floats2half2_rn(fmaxf(ac[2], 0.f), fmaxf(ac[3], 0.f));
            } else {
                h0 = __floats2half2_rn(ac[0], ac[1]);
                h1 = __floats2half2_rn(ac[2], ac[3]);
            }
            *(__half2*)(Ch + (size_t)r * N + c)       = h0;
            *(__half2*)(Ch + (size_t)(r + 8) * N + c) = h1;
        }
    }
}

// ---------------- fused GEMM + residual + LayerNorm (N fixed = 256) ----------------
#define LN_ABYTES (64*ASTR*2)
#define LN_BBYTES (256*ASTR*2)
#define LN_STAGE  (LN_ABYTES+LN_BBYTES)
#define LN_SMEM   (3*LN_STAGE)

template<bool HOUT>
__global__ void __launch_bounds__(256, 2)
hgemm_ln_k(const __half* __restrict__ A, const __half* __restrict__ B,
           const float* __restrict__ res, float* __restrict__ Of,
           __half* __restrict__ Oh, int M, int K) {
    extern __shared__ __half sm[];
    const int tid = threadIdx.x, lane = tid & 31, wid = tid >> 5;
    const int bm = blockIdx.x << 6;
    const uint32_t base = s2u(sm);
    const int wm = (wid >> 2) << 5, wn = (wid & 3) << 6;

    const int ar = tid >> 2, ac = (tid & 3) * 8;
    const __half* Ag = A + (size_t)(bm + ar) * K + ac;
    const uint32_t aDst = base + (uint32_t)(ar * ASTR + ac) * 2;

    float acc[2][8][4];
    #pragma unroll
    for (int i = 0; i < 2; i++)
        #pragma unroll
        for (int j = 0; j < 8; j++)
            #pragma unroll
            for (int q = 0; q < 4; q++) acc[i][j][q] = 0.f;

    const int nk = K >> 5;

    auto fill = [&](int st, int k0) {
        const uint32_t so = (uint32_t)st * LN_STAGE;
        cpa16(aDst + so, Ag + k0);
        #pragma unroll
        for (int j2 = 0; j2 < 4; j2++) {
            int idx = j2 * 256 + tid;
            int br = idx >> 2, bc = (idx & 3) * 8;
            cpa16(base + so + LN_ABYTES + (uint32_t)(br * ASTR + bc) * 2,
                  B + (size_t)br * K + k0 + bc);
        }
        asm volatile("cp.async.commit_group;");
    };

    fill(0, 0);
    fill(1, 32);

    const int krow = lane & 15, kh = (lane >> 4) * 8;
    const uint32_t aW = (uint32_t)((wm + krow) * ASTR + kh) * 2;
    const uint32_t bW = (uint32_t)((wn + krow) * ASTR + kh) * 2 + LN_ABYTES;

    int slot = 0;
    for (int j = 0; j < nk; j++) {
        asm volatile("cp.async.wait_group 1;");
        __syncthreads();
        const uint32_t so = (uint32_t)slot * LN_STAGE;
        const uint32_t aS = base + so + aW;
        const uint32_t bS = base + so + bW;

        uint32_t a0[2][4], b0[4][4];
        #pragma unroll
        for (int mf = 0; mf < 2; mf++)
            ldsm4(a0[mf][0], a0[mf][1], a0[mf][2], a0[mf][3],
                  aS + (uint32_t)(mf * 16 * ASTR) * 2);
        #pragma unroll
        for (int bf = 0; bf < 4; bf++)
            ldsm4(b0[bf][0], b0[bf][1], b0[bf][2], b0[bf][3],
                  bS + (uint32_t)(bf * 16 * ASTR) * 2);

        const int p = j + 2;
        if (p < nk) fill((slot + 2) % 3, p * 32);
        else asm volatile("cp.async.commit_group;");

        #pragma unroll
        for (int mf = 0; mf < 2; mf++)
            #pragma unroll
            for (int nf = 0; nf < 8; nf++)
                mma16816(acc[mf][nf], a0[mf],
                         b0[nf >> 1][nf & 1], b0[nf >> 1][2 + (nf & 1)]);

        uint32_t a1[2][4], b1[4][4];
        #pragma unroll
        for (int mf = 0; mf < 2; mf++)
            ldsm4(a1[mf][0], a1[mf][1], a1[mf][2], a1[mf][3],
                  aS + (uint32_t)(mf * 16 * ASTR + 16) * 2);
        #pragma unroll
        for (int bf = 0; bf < 4; bf++)
            ldsm4(b1[bf][0], b1[bf][1], b1[bf][2], b1[bf][3],
                  bS + (uint32_t)(bf * 16 * ASTR + 16) * 2);
        #pragma unroll
        for (int mf = 0; mf < 2; mf++)
            #pragma unroll
            for (int nf = 0; nf < 8; nf++)
                mma16816(acc[mf][nf], a1[mf],
                         b1[nf >> 1][nf & 1], b1[nf >> 1][2 + (nf & 1)]);

        slot++; if (slot == 3) slot = 0;
    }

    __syncthreads();

    float* stg = (float*)sm;
    const int r0 = wm + (lane >> 2), c0 = wn + (lane & 3) * 2;
    #pragma unroll
    for (int mf = 0; mf < 2; mf++) {
        #pragma unroll
        for (int nf = 0; nf < 8; nf++) {
            const int r = r0 + mf * 16, c = c0 + nf * 8;
            float* ac = acc[mf][nf];
            stg[r * 260 + c]           = ac[0];
            stg[r * 260 + c + 1]       = ac[1];
            stg[(r + 8) * 260 + c]     = ac[2];
            stg[(r + 8) * 260 + c + 1] = ac[3];
        }
    }
    __syncthreads();

    #pragma unroll
    for (int rr = 0; rr < 8; rr++) {
        const int r = wid * 8 + rr;
        const size_t gr = (size_t)(bm + r) * 256;
        float v[8];
        float sum = 0.f;
        #pragma unroll
        for (int q = 0; q < 8; q++) {
            v[q] = stg[r * 260 + lane + q * 32] + res[gr + lane + q * 32];
            sum += v[q];
        }
        #pragma unroll
        for (int off = 16; off; off >>= 1) sum += __shfl_xor_sync(0xffffffffu, sum, off);
        const float mean = sum * (1.f / 256.f);
        float sq = 0.f;
        #pragma unroll
        for (int q = 0; q < 8; q++) { float d = v[q] - mean; sq += d * d; }
        #pragma unroll
        for (int off = 16; off; off >>= 1) sq += __shfl_xor_sync(0xffffffffu, sq, off);
        const float rs = rsqrtf(sq * (1.f / 256.f) + 1e-5f);
        #pragma unroll
        for (int q = 0; q < 8; q++) {
            const float o = (v[q] - mean) * rs;
            Of[gr + lane + q * 32] = o;
            if (HOUT) Oh[gr + lane + q * 32] = __float2half_rn(o);
        }
    }
}

// ---------------- attention v2: K/V fp32 smem (vectorized), Q from gmem ----------------
// One block per word, one warp per head, lane = query row. d processed in two
// 16-wide chunks to keep registers low. Masked rows are a prefix; wlen is
// uniform per block so `j < wlen` branches are non-divergent skips.
template<int LT, bool MASKED>
__global__ void __launch_bounds__(256, 3) attn_k(const __half* __restrict__ qkv,
                                                 const int* __restrict__ toks,
                                                 __half* __restrict__ out) {
    extern __shared__ float skv[];            // K: [LT][256], V: [LT][256]
    float* sK = skv;
    float* sV = skv + LT * 256;
    const int w = blockIdx.x, tid = threadIdx.x;
    const int h = tid >> 5, lane = tid & 31;
    const __half* base = qkv + (size_t)w * LT * 768;

    // stage K+V fp16 -> fp32 smem (vectorized)
    for (int i = tid; i < LT * 64; i += 256) {
        const int j = i >> 6;
        const int c8 = (i & 63) * 8;          // half col within [0,512)
        uint4 v = *(const uint4*)(base + j * 768 + 256 + c8);
        const __half2* hp = (const __half2*)&v;
        float2 f0 = __half22float2(hp[0]);
        float2 f1 = __half22float2(hp[1]);
        float2 f2 = __half22float2(hp[2]);
        float2 f3 = __half22float2(hp[3]);
        float* dst = (c8 < 256) ? (sK + j * 256 + c8) : (sV + j * 256 + c8 - 256);
        *(float4*)dst       = make_float4(f0.x, f0.y, f1.x, f1.y);
        *(float4*)(dst + 4) = make_float4(f2.x, f2.y, f3.x, f3.y);
    }

    int wlen = LT;
    if (MASKED) {
        const int valid = (lane < LT) && (toks[(size_t)w * LT + lane] != 0);
        wlen = __popc(__ballot_sync(0xffffffffu, valid));
    }
    __syncthreads();

    if (lane < LT) {
        const __half* qp = base + (size_t)lane * 768 + h * HD;

        // ---- scores: two d-chunks of 16, accumulate into p[] ----
        float p[LT];
        #pragma unroll
        for (int j = 0; j < LT; j++) p[j] = 0.f;

        #pragma unroll
        for (int dc = 0; dc < 2; dc++) {
            float q[16];
            uint4 qv0 = *(const uint4*)(qp + dc * 16);
            uint4 qv1 = *(const uint4*)(qp + dc * 16 + 8);
            const __half2* h0 = (const __half2*)&qv0;
            const __half2* h1 = (const __half2*)&qv1;
            #pragma unroll
            for (int t = 0; t < 4; t++) {
                float2 f0 = __half22float2(h0[t]);
                float2 f1 = __half22float2(h1[t]);
                q[2 * t]     = f0.x; q[2 * t + 1]     = f0.y;
                q[8 + 2 * t] = f1.x; q[8 + 2 * t + 1] = f1.y;
            }
            #pragma unroll
            for (int j = 0; j < LT; j++) {
                if (j < wlen) {
                    const float* kp = sK + j * 256 + h * HD + dc * 16;
                    float a = 0.f;
                    #pragma unroll
                    for (int f = 0; f < 4; f++) {
                        float4 kv = *(const float4*)(kp + f * 4);
                        a += q[4 * f] * kv.x + q[4 * f + 1] * kv.y
                           + q[4 * f + 2] * kv.z + q[4 * f + 3] * kv.w;
                    }
                    p[j] += a;
                }
            }
        }

        // ---- softmax over valid rows ----
        float mx = -1e30f;
        #pragma unroll
        for (int j = 0; j < LT; j++)
            if (j < wlen) mx = fmaxf(mx, p[j] * 0.17677669529663687f);
        float sum = 0.f;
        #pragma unroll
        for (int j = 0; j < LT; j++) {
            if (j < wlen) {
                p[j] = expf(p[j] * 0.17677669529663687f - mx);
                sum += p[j];
            }
        }
        const float inv = 1.f / sum;

        // ---- A@V: two d-chunks of 16 ----
        __half* op = out + ((size_t)w * LT + lane) * D + h * HD;
        #pragma unroll
        for (int dc = 0; dc < 2; dc++) {
            float acc[16];
            #pragma unroll
            for (int d = 0; d < 16; d++) acc[d] = 0.f;
            #pragma unroll
            for (int j = 0; j < LT; j++) {
                if (j < wlen) {
                    const float* vp = sV + j * 256 + h * HD + dc * 16;
                    const float pj = p[j];
                    #pragma unroll
                    for (int f = 0; f < 4; f++) {
                        float4 vv = *(const float4*)(vp + f * 4);
                        acc[4 * f]     += pj * vv.x;
                        acc[4 * f + 1] += pj * vv.y;
                        acc[4 * f + 2] += pj * vv.z;
                        acc[4 * f + 3] += pj * vv.w;
                    }
                }
            }
            uint4 ov;
            __half2* oh = (__half2*)&ov;
            #pragma unroll
            for (int t = 0; t < 4; t++)
                oh[t] = __floats2half2_rn(acc[2 * t] * inv, acc[2 * t + 1] * inv);
            *(uint4*)(op + dc * 16) = ov;
            #pragma unroll
            for (int t = 0; t < 4; t++)
                oh[t] = __floats2half2_rn(acc[8 + 2 * t] * inv, acc[9 + 2 * t] * inv);
            *(uint4*)(op + dc * 16 + 8) = ov;
        }
    }
}

// ---------------- masked mean over chars + scatter into padded ----------------
__global__ void pool_k(const float* __restrict__ wft, const int* __restrict__ toks,
                       const int* __restrict__ cid, const int* __restrict__ wpos,
                       float* __restrict__ pad, __half* __restrict__ padh) {
    const int w = blockIdx.x, d = threadIdx.x;
    __shared__ int val[LW];
    if (d < LW) val[d] = (toks[(size_t)w * LW + d] != 0);
    __syncthreads();
    float ssum = 0.f; int cnt = 0;
    #pragma unroll
    for (int j = 0; j < LW; j++) {
        if (val[j]) { ssum += wft[((size_t)w * LW + j) * D + d]; cnt++; }
    }
    const float r = ssum / (float)cnt;
    const size_t oi = ((size_t)cid[w] * MAXW + wpos[w]) * D + d;
    pad[oi]  = r;
    padh[oi] = __float2half_rn(r);
}

// ---------------- final pooling ----------------
__global__ void final_k(const float* __restrict__ nf, const float* __restrict__ pad,
                        float* __restrict__ out) {
    const int c = blockIdx.x, d = threadIdx.x;
    __shared__ int nz[MAXW];
    if (d < MAXW) nz[d] = 0;
    __syncthreads();
    #pragma unroll
    for (int w = 0; w < MAXW; w++) {
        if (pad[((size_t)c * MAXW + w) * D + d] != 0.f) atomicOr(&nz[w], 1);
    }
    __syncthreads();
    float ssum = 0.f; int cnt = 0;
    #pragma unroll
    for (int w = 0; w < MAXW; w++) {
        if (nz[w]) {
            float v = nf[((size_t)c * MAXW + w) * D + d];
            ssum += v;
            cnt += (v != 0.f);
        }
    }
    out[(size_t)c * D + d] = ssum / (float)cnt;
}

// ---------------- driver ----------------
extern "C" void kernel_launch(void* const* d_in, const int* in_sizes, int n_in,
                              void* d_out, int out_size) {
    const int* toks = (const int*)d_in[0];
    const int* cid  = (const int*)d_in[1];
    const int* wpos = (const int*)d_in[2];

    int wi = 3;
    while (wi < n_in && in_sizes[wi] != 128 * 256) wi++;
    const float* we_emb = (const float*)d_in[wi + 0];
    const float* we_qkv = (const float*)d_in[wi + 1];
    const float* we_o   = (const float*)d_in[wi + 2];
    const float* we_ff1 = (const float*)d_in[wi + 3];
    const float* we_ff2 = (const float*)d_in[wi + 4];
    const float* ne_qkv = (const float*)d_in[wi + 5];
    const float* ne_o   = (const float*)d_in[wi + 6];
    const float* ne_ff1 = (const float*)d_in[wi + 7];
    const float* ne_ff2 = (const float*)d_in[wi + 8];
    float* out = (float*)d_out;

    float *x, *qkvf, *h, *nf, *pad;
    __half *xh, *ah, *hh, *ffh, *padh, *wh;
    cudaGetSymbolAddress((void**)&x,    g_x);
    cudaGetSymbolAddress((void**)&qkvf, g_qkv);
    cudaGetSymbolAddress((void**)&h,    g_h);
    cudaGetSymbolAddress((void**)&nf,   g_nf);
    cudaGetSymbolAddress((void**)&pad,  g_pad);
    cudaGetSymbolAddress((void**)&xh,   g_xh);
    cudaGetSymbolAddress((void**)&ah,   g_ah);
    cudaGetSymbolAddress((void**)&hh,   g_hh);
    cudaGetSymbolAddress((void**)&ffh,  g_ffh);
    cudaGetSymbolAddress((void**)&padh, g_padh);
    cudaGetSymbolAddress((void**)&wh,   g_wh);
    __half* qkvh = (__half*)qkvf;

    cudaFuncSetAttribute(hgemm_k<1>, cudaFuncAttributeMaxDynamicSharedMemorySize, HSME);
    cudaFuncSetAttribute(hgemm_k<2>, cudaFuncAttributeMaxDynamicSharedMemorySize, HSME);
    cudaFuncSetAttribute(hgemm_ln_k<true>,
                         cudaFuncAttributeMaxDynamicSharedMemorySize, LN_SMEM);
    cudaFuncSetAttribute(hgemm_ln_k<false>,
                         cudaFuncAttributeMaxDynamicSharedMemorySize, LN_SMEM);
    cudaFuncSetAttribute(attn_k<LW, true>,
                         cudaFuncAttributeMaxDynamicSharedMemorySize, LW * 512 * 4);
    cudaFuncSetAttribute(attn_k<MAXW, false>,
                         cudaFuncAttributeMaxDynamicSharedMemorySize, MAXW * 512 * 4);

    auto WC = [&](const float* W, size_t off, int K, int N) {
        wconv_k<<<(K * N + 255) / 256, 256>>>(W, wh + off, K, N);
    };

    // ===== block 1 (char transformer, 196608 tokens) =====
    WC(we_qkv, 0, D, 3 * D);                                                   // 0
    embed_k<<<(M1 * D + 255) / 256, 256>>>(toks, we_emb, x, xh, M1 * D);       // 1
    hgemm_k<2><<<dim3(6, M1 / 128), 256, HSME>>>(xh, wh, qkvh, M1, 3 * D, D);  // 2
    attn_k<LW, true><<<NW, 256, LW * 512 * 4>>>(qkvh, toks, ah);               // 3
    WC(we_o, 196608, D, D);                                                    // 4
    hgemm_ln_k<true><<<M1 / 64, 256, LN_SMEM>>>(ah, wh + 196608, x, h, hh, M1, D);   // 5 (profiled)
    WC(we_ff1, 262144, D, DFF);                                                // 6
    hgemm_k<1><<<dim3(8, M1 / 128), 256, HSME>>>(hh, wh + 262144, ffh, M1, DFF, D);  // 7
    WC(we_ff2, 524288, DFF, D);                                                // 8
    hgemm_ln_k<false><<<M1 / 64, 256, LN_SMEM>>>(ffh, wh + 524288, h, x, nullptr, M1, DFF); // 9

    // ===== pool chars -> words, scatter into padded [NC, MAXW, D] =====
    zero2_k<<<(M2 * D + 255) / 256, 256>>>(pad, padh, M2 * D);
    pool_k<<<NW, 256>>>(x, toks, cid, wpos, pad, padh);

    // ===== block 2 (name transformer, 16384 tokens) =====
    WC(ne_qkv, 786432, D, 3 * D);
    hgemm_k<2><<<dim3(6, M2 / 128), 256, HSME>>>(padh, wh + 786432, qkvh, M2, 3 * D, D);
    attn_k<MAXW, false><<<NC, 256, MAXW * 512 * 4>>>(qkvh, nullptr, ah);
    WC(ne_o, 983040, D, D);
    hgemm_ln_k<true><<<M2 / 64, 256, LN_SMEM>>>(ah, wh + 983040, pad, h, hh, M2, D);
    WC(ne_ff1, 1048576, D, DFF);
    hgemm_k<1><<<dim3(8, M2 / 128), 256, HSME>>>(hh, wh + 1048576, ffh, M2, DFF, D);
    WC(ne_ff2, 1310720, DFF, D);
    hgemm_ln_k<false><<<M2 / 64, 256, LN_SMEM>>>(ffh, wh + 1310720, h, nf, nullptr, M2, DFF);

    // ===== final pooling -> output =====
    final_k<<<NC, 256>>>(nf, pad, out);
}

// round 17
// speedup vs baseline: 6.4969x; 1.4585x over previous
#include <cuda_runtime.h>
#include <cuda_fp16.h>
#include <cstddef>
#include <cstdint>

// ---------------- problem constants ----------------
#define NW    8192
#define LW    24
#define D     256
#define NH    8
#define HD    32
#define DFF   1024
#define NC    1024
#define MAXW  16
#define M1    (NW*LW)       // 196608 max tokens, block 1
#define M1P   (M1+128)      // + tail pad
#define M2    (NC*MAXW)     // 16384 tokens, block 2

// ---------------- scratch (device globals; no cudaMalloc allowed) ----------------
__device__ float  g_x   [(size_t)M1P*D];
__device__ __half g_qkv [(size_t)M1P*3*D];  // fp16 qkv
__device__ float  g_h   [(size_t)M1P*D];
__device__ float  g_nf  [(size_t)M2*D];     // name_ft (block2 only)
__device__ __half g_xh  [(size_t)M1P*D];
__device__ __half g_ah  [(size_t)M1P*D];
__device__ __half g_hh  [(size_t)M1P*D];
__device__ __half g_ffh [(size_t)M1P*DFF];
__device__ float  g_pad [(size_t)M2*D];
__device__ __half g_padh[(size_t)M2*D];

__device__ int g_off[NW + 1];   // compacted row offset per word
__device__ int g_mvp;           // valid rows rounded up to 128

// transposed fp16 weights, [N][K] K-major
#define W_TOTAL 1572864
__device__ __half g_wh[W_TOTAL];

// ---------------- word-length prefix sum (valid chars are a prefix) ----------------
__global__ void __launch_bounds__(1024) scan_k(const int* __restrict__ toks) {
    __shared__ int ssum[1024];
    const int t = threadIdx.x;
    int lens[8], loc = 0;
    #pragma unroll
    for (int i = 0; i < 8; i++) {
        const int w = t * 8 + i;
        int l = 0;
        #pragma unroll
        for (int c = 0; c < LW; c++) l += (toks[(size_t)w * LW + c] != 0);
        lens[i] = l; loc += l;
    }
    ssum[t] = loc;
    __syncthreads();
    for (int off = 1; off < 1024; off <<= 1) {
        int v = (t >= off) ? ssum[t - off] : 0;
        __syncthreads();
        ssum[t] += v;
        __syncthreads();
    }
    int base = ssum[t] - loc;
    #pragma unroll
    for (int i = 0; i < 8; i++) {
        g_off[t * 8 + i] = base;
        base += lens[i];
    }
    if (t == 1023) {
        g_off[NW] = base;
        g_mvp = (base + 127) & ~127;
    }
}

// ---------------- weight transpose fp32 [K,N] -> fp16 [N][K] ----------------
__global__ void wconv_k(const float* __restrict__ W, __half* __restrict__ wh,
                        int K, int N) {
    int i = blockIdx.x * blockDim.x + threadIdx.x;
    if (i < K * N) {
        int n = i % N, k = i / N;
        wh[(size_t)n * K + k] = __float2half_rn(W[i]);
    }
}

// ---------------- compacted embedding gather ----------------
__global__ void embed2_k(const int* __restrict__ toks, const float* __restrict__ emb,
                         float* __restrict__ x, __half* __restrict__ xh) {
    const int w = blockIdx.x, d = threadIdx.x;
    const int o = g_off[w], len = g_off[w + 1] - o;
    for (int r = 0; r < len; r++) {
        const float v = emb[toks[(size_t)w * LW + r] * D + d];
        const size_t idx = (size_t)(o + r) * D + d;
        x[idx] = v;
        xh[idx] = __float2half_rn(v);
    }
}

// zero tail rows [mv, mvp) of the GEMM A-side inputs + residual
__global__ void ztail_k(float* __restrict__ x, __half* __restrict__ xh,
                        __half* __restrict__ ah, __half* __restrict__ hh) {
    const int row = g_off[NW] + blockIdx.x;
    if (row < g_mvp) {
        const size_t idx = (size_t)row * D + threadIdx.x;
        x[idx] = 0.f;
        const __half z = __float2half_rn(0.f);
        xh[idx] = z; ah[idx] = z; hh[idx] = z;
    }
}

__global__ void zero2_k(float* __restrict__ p, __half* __restrict__ ph, int n) {
    int i = blockIdx.x * blockDim.x + threadIdx.x;
    if (i < n) { p[i] = 0.f; ph[i] = __float2half_rn(0.f); }
}

// ================= helpers =================
__device__ __forceinline__ uint32_t s2u(const void* p) {
    uint32_t a;
    asm("{ .reg .u64 t; cvta.to.shared.u64 t, %1; cvt.u32.u64 %0, t; }" : "=r"(a) : "l"(p));
    return a;
}
__device__ __forceinline__ void cpa16(uint32_t dst, const void* src) {
    asm volatile("cp.async.cg.shared.global [%0], [%1], 16;" :: "r"(dst), "l"(src));
}
__device__ __forceinline__ void ldsm4(uint32_t& r0, uint32_t& r1, uint32_t& r2,
                                      uint32_t& r3, uint32_t a) {
    asm volatile("ldmatrix.sync.aligned.m8n8.x4.shared.b16 {%0,%1,%2,%3}, [%4];"
                 : "=r"(r0), "=r"(r1), "=r"(r2), "=r"(r3) : "r"(a));
}
__device__ __forceinline__ void mma16816(float* c, const uint32_t* a,
                                         uint32_t b0, uint32_t b1) {
    asm volatile(
        "mma.sync.aligned.m16n8k16.row.col.f32.f16.f16.f32 "
        "{%0,%1,%2,%3}, {%4,%5,%6,%7}, {%8,%9}, {%0,%1,%2,%3};"
        : "+f"(c[0]), "+f"(c[1]), "+f"(c[2]), "+f"(c[3])
        : "r"(a[0]), "r"(a[1]), "r"(a[2]), "r"(a[3]), "r"(b0), "r"(b1));
}

// ---------------- fp16 tensor-core GEMM ----------------
#define ASTR 40
#define SLOT (128*ASTR)
#define HSME (4*SLOT*2*2)

template<int MODE, bool RAGGED>   // MODE 1: relu+fp16 out, 2: fp16 out
__global__ void __launch_bounds__(256, 2) hgemm_k(const __half* __restrict__ A,
                                                  const __half* __restrict__ B,
                                                  __half* __restrict__ Ch,
                                                  int M, int N, int K) {
    const int bm = blockIdx.y << 7, bn = blockIdx.x << 7;
    if (RAGGED && bm >= g_mvp) return;

    extern __shared__ __half sm[];
    const int tid = threadIdx.x, lane = tid & 31, wid = tid >> 5;
    const int wm = (wid & 1) << 6, wn = (wid >> 1) << 5;

    __half* Bsl = sm + 4 * SLOT;
    const uint32_t aBase = s2u(sm), bBase = s2u(Bsl);

    const int lr = tid >> 1;
    const int lc = (tid & 1) * 16;
    const __half* Ag = A + (size_t)(bm + lr) * K + lc;
    const __half* Bg = B + (size_t)(bn + lr) * K + lc;
    const uint32_t aDst = aBase + (uint32_t)(lr * ASTR + lc) * 2;
    const uint32_t bDst = bBase + (uint32_t)(lr * ASTR + lc) * 2;
    const uint32_t slotB = SLOT * 2;

    float acc[4][4][4];
    #pragma unroll
    for (int i = 0; i < 4; i++)
        #pragma unroll
        for (int j = 0; j < 4; j++)
            #pragma unroll
            for (int q = 0; q < 4; q++) acc[i][j][q] = 0.f;

    const int nk = K >> 5;
    #pragma unroll
    for (int s = 0; s < 3; s++) {
        cpa16(aDst + s * slotB,      Ag + s * 32);
        cpa16(aDst + s * slotB + 16, Ag + s * 32 + 8);
        cpa16(bDst + s * slotB,      Bg + s * 32);
        cpa16(bDst + s * slotB + 16, Bg + s * 32 + 8);
        asm volatile("cp.async.commit_group;");
    }

    const int krow = lane & 15, kh = (lane >> 4) * 8;
    const uint32_t aW = (uint32_t)((wm + krow) * ASTR + kh) * 2;
    const uint32_t bW = (uint32_t)((wn + krow) * ASTR + kh) * 2;

    for (int j = 0; j < nk; j++) {
        asm volatile("cp.async.wait_group 2;");
        __syncthreads();

        const uint32_t aS = aBase + (uint32_t)(j & 3) * slotB + aW;
        const uint32_t bS = bBase + (uint32_t)(j & 3) * slotB + bW;

        uint32_t a[2][4][4], b[2][2][4];
        #pragma unroll
        for (int k16 = 0; k16 < 2; k16++) {
            #pragma unroll
            for (int mf = 0; mf < 4; mf++)
                ldsm4(a[k16][mf][0], a[k16][mf][1], a[k16][mf][2], a[k16][mf][3],
                      aS + (uint32_t)(mf * 16 * ASTR + k16 * 16) * 2);
            #pragma unroll
            for (int bf = 0; bf < 2; bf++)
                ldsm4(b[k16][bf][0], b[k16][bf][1], b[k16][bf][2], b[k16][bf][3],
                      bS + (uint32_t)(bf * 16 * ASTR + k16 * 16) * 2);
        }

        const int p = j + 3;
        if (p < nk) {
            const int sl = p & 3;
            cpa16(aDst + sl * slotB,      Ag + p * 32);
            cpa16(aDst + sl * slotB + 16, Ag + p * 32 + 8);
            cpa16(bDst + sl * slotB,      Bg + p * 32);
            cpa16(bDst + sl * slotB + 16, Bg + p * 32 + 8);
        }
        asm volatile("cp.async.commit_group;");

        #pragma unroll
        for (int k16 = 0; k16 < 2; k16++)
            #pragma unroll
            for (int mf = 0; mf < 4; mf++)
                #pragma unroll
                for (int nf = 0; nf < 4; nf++)
                    mma16816(acc[mf][nf], a[k16][mf],
                             b[k16][nf >> 1][nf & 1], b[k16][nf >> 1][2 + (nf & 1)]);
    }

    const int r0 = bm + wm + (lane >> 2);
    const int c0 = bn + wn + (lane & 3) * 2;
    #pragma unroll
    for (int mf = 0; mf < 4; mf++) {
        #pragma unroll
        for (int nf = 0; nf < 4; nf++) {
            const int r = r0 + mf * 16, c = c0 + nf * 8;
            float* ac = acc[mf][nf];
            __half2 h0, h1;
            if (MODE == 1) {
                h0 = __floats2half2_rn(fmaxf(ac[0], 0.f), fmaxf(ac[1], 0.f));
                h1 = __floats2half2_rn(fmaxf(ac[2], 0.f), fmaxf(ac[3], 0.f));
            } else {
                h0 = __floats2half2_rn(ac[0], ac[1]);
                h1 = __floats2half2_rn(ac[2], ac[3]);
            }
            *(__half2*)(Ch + (size_t)r * N + c)       = h0;
            *(__half2*)(Ch + (size_t)(r + 8) * N + c) = h1;
        }
    }
}

// ---------------- fused GEMM + residual + LayerNorm (N fixed = 256) ----------------
#define LN_ABYTES (64*ASTR*2)
#define LN_BBYTES (256*ASTR*2)
#define LN_STAGE  (LN_ABYTES+LN_BBYTES)
#define LN_SMEM   (3*LN_STAGE)

template<bool HOUT, bool RAGGED>
__global__ void __launch_bounds__(256, 2)
hgemm_ln_k(const __half* __restrict__ A, const __half* __restrict__ B,
           const float* __restrict__ res, float* __restrict__ Of,
           __half* __restrict__ Oh, int M, int K) {
    const int bm = blockIdx.x << 6;
    if (RAGGED && bm >= g_mvp) return;

    extern __shared__ __half sm[];
    const int tid = threadIdx.x, lane = tid & 31, wid = tid >> 5;
    const uint32_t base = s2u(sm);
    const int wm = (wid >> 2) << 5, wn = (wid & 3) << 6;

    const int ar = tid >> 2, ac = (tid & 3) * 8;
    const __half* Ag = A + (size_t)(bm + ar) * K + ac;
    const uint32_t aDst = base + (uint32_t)(ar * ASTR + ac) * 2;

    float acc[2][8][4];
    #pragma unroll
    for (int i = 0; i < 2; i++)
        #pragma unroll
        for (int j = 0; j < 8; j++)
            #pragma unroll
            for (int q = 0; q < 4; q++) acc[i][j][q] = 0.f;

    const int nk = K >> 5;

    auto fill = [&](int st, int k0) {
        const uint32_t so = (uint32_t)st * LN_STAGE;
        cpa16(aDst + so, Ag + k0);
        #pragma unroll
        for (int j2 = 0; j2 < 4; j2++) {
            int idx = j2 * 256 + tid;
            int br = idx >> 2, bc = (idx & 3) * 8;
            cpa16(base + so + LN_ABYTES + (uint32_t)(br * ASTR + bc) * 2,
                  B + (size_t)br * K + k0 + bc);
        }
        asm volatile("cp.async.commit_group;");
    };

    fill(0, 0);
    fill(1, 32);

    const int krow = lane & 15, kh = (lane >> 4) * 8;
    const uint32_t aW = (uint32_t)((wm + krow) * ASTR + kh) * 2;
    const uint32_t bW = (uint32_t)((wn + krow) * ASTR + kh) * 2 + LN_ABYTES;

    int slot = 0;
    for (int j = 0; j < nk; j++) {
        asm volatile("cp.async.wait_group 1;");
        __syncthreads();
        const uint32_t so = (uint32_t)slot * LN_STAGE;
        const uint32_t aS = base + so + aW;
        const uint32_t bS = base + so + bW;

        uint32_t a0[2][4], b0[4][4];
        #pragma unroll
        for (int mf = 0; mf < 2; mf++)
            ldsm4(a0[mf][0], a0[mf][1], a0[mf][2], a0[mf][3],
                  aS + (uint32_t)(mf * 16 * ASTR) * 2);
        #pragma unroll
        for (int bf = 0; bf < 4; bf++)
            ldsm4(b0[bf][0], b0[bf][1], b0[bf][2], b0[bf][3],
                  bS + (uint32_t)(bf * 16 * ASTR) * 2);

        const int p = j + 2;
        if (p < nk) fill((slot + 2) % 3, p * 32);
        else asm volatile("cp.async.commit_group;");

        #pragma unroll
        for (int mf = 0; mf < 2; mf++)
            #pragma unroll
            for (int nf = 0; nf < 8; nf++)
                mma16816(acc[mf][nf], a0[mf],
                         b0[nf >> 1][nf & 1], b0[nf >> 1][2 + (nf & 1)]);

        uint32_t a1[2][4], b1[4][4];
        #pragma unroll
        for (int mf = 0; mf < 2; mf++)
            ldsm4(a1[mf][0], a1[mf][1], a1[mf][2], a1[mf][3],
                  aS + (uint32_t)(mf * 16 * ASTR + 16) * 2);
        #pragma unroll
        for (int bf = 0; bf < 4; bf++)
            ldsm4(b1[bf][0], b1[bf][1], b1[bf][2], b1[bf][3],
                  bS + (uint32_t)(bf * 16 * ASTR + 16) * 2);
        #pragma unroll
        for (int mf = 0; mf < 2; mf++)
            #pragma unroll
            for (int nf = 0; nf < 8; nf++)
                mma16816(acc[mf][nf], a1[mf],
                         b1[nf >> 1][nf & 1], b1[nf >> 1][2 + (nf & 1)]);

        slot++; if (slot == 3) slot = 0;
    }

    __syncthreads();

    float* stg = (float*)sm;
    const int r0 = wm + (lane >> 2), c0 = wn + (lane & 3) * 2;
    #pragma unroll
    for (int mf = 0; mf < 2; mf++) {
        #pragma unroll
        for (int nf = 0; nf < 8; nf++) {
            const int r = r0 + mf * 16, c = c0 + nf * 8;
            float* ac = acc[mf][nf];
            stg[r * 260 + c]           = ac[0];
            stg[r * 260 + c + 1]       = ac[1];
            stg[(r + 8) * 260 + c]     = ac[2];
            stg[(r + 8) * 260 + c + 1] = ac[3];
        }
    }
    __syncthreads();

    #pragma unroll
    for (int rr = 0; rr < 8; rr++) {
        const int r = wid * 8 + rr;
        const size_t gr = (size_t)(bm + r) * 256;
        float v[8];
        float sum = 0.f;
        #pragma unroll
        for (int q = 0; q < 8; q++) {
            v[q] = stg[r * 260 + lane + q * 32] + res[gr + lane + q * 32];
            sum += v[q];
        }
        #pragma unroll
        for (int off = 16; off; off >>= 1) sum += __shfl_xor_sync(0xffffffffu, sum, off);
        const float mean = sum * (1.f / 256.f);
        float sq = 0.f;
        #pragma unroll
        for (int q = 0; q < 8; q++) { float d = v[q] - mean; sq += d * d; }
        #pragma unroll
        for (int off = 16; off; off >>= 1) sq += __shfl_xor_sync(0xffffffffu, sq, off);
        const float rs = rsqrtf(sq * (1.f / 256.f) + 1e-5f);
        #pragma unroll
        for (int q = 0; q < 8; q++) {
            const float o = (v[q] - mean) * rs;
            Of[gr + lane + q * 32] = o;
            if (HOUT) Oh[gr + lane + q * 32] = __float2half_rn(o);
        }
    }
}

// ---------------- attention: compacted rows, K/V fp32 smem, Q from gmem ----------------
template<int LT, bool RAGGED>
__global__ void __launch_bounds__(256, 3) attn_k(const __half* __restrict__ qkv,
                                                 __half* __restrict__ out) {
    extern __shared__ float skv[];            // K: [LT][256], V: [LT][256]
    float* sK = skv;
    float* sV = skv + LT * 256;
    const int w = blockIdx.x, tid = threadIdx.x;
    const int h = tid >> 5, lane = tid & 31;

    int o, len;
    if (RAGGED) { o = g_off[w]; len = g_off[w + 1] - o; }
    else        { o = w * LT;   len = LT; }
    const __half* base = qkv + (size_t)o * 768;

    for (int i = tid; i < len * 64; i += 256) {
        const int j = i >> 6;
        const int c8 = (i & 63) * 8;
        uint4 v = *(const uint4*)(base + j * 768 + 256 + c8);
        const __half2* hp = (const __half2*)&v;
        float2 f0 = __half22float2(hp[0]);
        float2 f1 = __half22float2(hp[1]);
        float2 f2 = __half22float2(hp[2]);
        float2 f3 = __half22float2(hp[3]);
        float* dst = (c8 < 256) ? (sK + j * 256 + c8) : (sV + j * 256 + c8 - 256);
        *(float4*)dst       = make_float4(f0.x, f0.y, f1.x, f1.y);
        *(float4*)(dst + 4) = make_float4(f2.x, f2.y, f3.x, f3.y);
    }
    __syncthreads();

    if (lane < len) {
        const __half* qp = base + (size_t)lane * 768 + h * HD;

        float p[LT];
        #pragma unroll
        for (int j = 0; j < LT; j++) p[j] = 0.f;

        #pragma unroll
        for (int dc = 0; dc < 2; dc++) {
            float q[16];
            uint4 qv0 = *(const uint4*)(qp + dc * 16);
            uint4 qv1 = *(const uint4*)(qp + dc * 16 + 8);
            const __half2* h0 = (const __half2*)&qv0;
            const __half2* h1 = (const __half2*)&qv1;
            #pragma unroll
            for (int t = 0; t < 4; t++) {
                float2 f0 = __half22float2(h0[t]);
                float2 f1 = __half22float2(h1[t]);
                q[2 * t]     = f0.x; q[2 * t + 1]     = f0.y;
                q[8 + 2 * t] = f1.x; q[8 + 2 * t + 1] = f1.y;
            }
            #pragma unroll
            for (int j = 0; j < LT; j++) {
                if (j < len) {
                    const float* kp = sK + j * 256 + h * HD + dc * 16;
                    float a = 0.f;
                    #pragma unroll
                    for (int f = 0; f < 4; f++) {
                        float4 kv = *(const float4*)(kp + f * 4);
                        a += q[4 * f] * kv.x + q[4 * f + 1] * kv.y
                           + q[4 * f + 2] * kv.z + q[4 * f + 3] * kv.w;
                    }
                    p[j] += a;
                }
            }
        }

        float mx = -1e30f;
        #pragma unroll
        for (int j = 0; j < LT; j++)
            if (j < len) mx = fmaxf(mx, p[j] * 0.17677669529663687f);
        float sum = 0.f;
        #pragma unroll
        for (int j = 0; j < LT; j++) {
            if (j < len) {
                p[j] = expf(p[j] * 0.17677669529663687f - mx);
                sum += p[j];
            }
        }
        const float inv = 1.f / sum;

        __half* op = out + (size_t)(o + lane) * D + h * HD;
        #pragma unroll
        for (int dc = 0; dc < 2; dc++) {
            float acc[16];
            #pragma unroll
            for (int d = 0; d < 16; d++) acc[d] = 0.f;
            #pragma unroll
            for (int j = 0; j < LT; j++) {
                if (j < len) {
                    const float* vp = sV + j * 256 + h * HD + dc * 16;
                    const float pj = p[j];
                    #pragma unroll
                    for (int f = 0; f < 4; f++) {
                        float4 vv = *(const float4*)(vp + f * 4);
                        acc[4 * f]     += pj * vv.x;
                        acc[4 * f + 1] += pj * vv.y;
                        acc[4 * f + 2] += pj * vv.z;
                        acc[4 * f + 3] += pj * vv.w;
                    }
                }
            }
            uint4 ov;
            __half2* oh = (__half2*)&ov;
            #pragma unroll
            for (int t = 0; t < 4; t++)
                oh[t] = __floats2half2_rn(acc[2 * t] * inv, acc[2 * t + 1] * inv);
            *(uint4*)(op + dc * 16) = ov;
            #pragma unroll
            for (int t = 0; t < 4; t++)
                oh[t] = __floats2half2_rn(acc[8 + 2 * t] * inv, acc[9 + 2 * t] * inv);
            *(uint4*)(op + dc * 16 + 8) = ov;
        }
    }
}

// ---------------- mean over word's compacted rows + scatter into padded ----------------
__global__ void pool2_k(const float* __restrict__ wft, const int* __restrict__ cid,
                        const int* __restrict__ wpos, float* __restrict__ pad,
                        __half* __restrict__ padh) {
    const int w = blockIdx.x, d = threadIdx.x;
    const int o = g_off[w], len = g_off[w + 1] - o;
    float ssum = 0.f;
    for (int r = 0; r < len; r++) ssum += wft[(size_t)(o + r) * D + d];
    const float r = ssum / (float)len;
    const size_t oi = ((size_t)cid[w] * MAXW + wpos[w]) * D + d;
    pad[oi]  = r;
    padh[oi] = __float2half_rn(r);
}

// ---------------- final pooling ----------------
__global__ void final_k(const float* __restrict__ nf, const float* __restrict__ pad,
                        float* __restrict__ out) {
    const int c = blockIdx.x, d = threadIdx.x;
    __shared__ int nz[MAXW];
    if (d < MAXW) nz[d] = 0;
    __syncthreads();
    #pragma unroll
    for (int w = 0; w < MAXW; w++) {
        if (pad[((size_t)c * MAXW + w) * D + d] != 0.f) atomicOr(&nz[w], 1);
    }
    __syncthreads();
    float ssum = 0.f; int cnt = 0;
    #pragma unroll
    for (int w = 0; w < MAXW; w++) {
        if (nz[w]) {
            float v = nf[((size_t)c * MAXW + w) * D + d];
            ssum += v;
            cnt += (v != 0.f);
        }
    }
    out[(size_t)c * D + d] = ssum / (float)cnt;
}

// ---------------- driver ----------------
extern "C" void kernel_launch(void* const* d_in, const int* in_sizes, int n_in,
                              void* d_out, int out_size) {
    const int* toks = (const int*)d_in[0];
    const int* cid  = (const int*)d_in[1];
    const int* wpos = (const int*)d_in[2];

    int wi = 3;
    while (wi < n_in && in_sizes[wi] != 128 * 256) wi++;
    const float* we_emb = (const float*)d_in[wi + 0];
    const float* we_qkv = (const float*)d_in[wi + 1];
    const float* we_o   = (const float*)d_in[wi + 2];
    const float* we_ff1 = (const float*)d_in[wi + 3];
    const float* we_ff2 = (const float*)d_in[wi + 4];
    const float* ne_qkv = (const float*)d_in[wi + 5];
    const float* ne_o   = (const float*)d_in[wi + 6];
    const float* ne_ff1 = (const float*)d_in[wi + 7];
    const float* ne_ff2 = (const float*)d_in[wi + 8];
    float* out = (float*)d_out;

    float *x, *h, *nf, *pad;
    __half *qkvh, *xh, *ah, *hh, *ffh, *padh, *wh;
    cudaGetSymbolAddress((void**)&x,    g_x);
    cudaGetSymbolAddress((void**)&qkvh, g_qkv);
    cudaGetSymbolAddress((void**)&h,    g_h);
    cudaGetSymbolAddress((void**)&nf,   g_nf);
    cudaGetSymbolAddress((void**)&pad,  g_pad);
    cudaGetSymbolAddress((void**)&xh,   g_xh);
    cudaGetSymbolAddress((void**)&ah,   g_ah);
    cudaGetSymbolAddress((void**)&hh,   g_hh);
    cudaGetSymbolAddress((void**)&ffh,  g_ffh);
    cudaGetSymbolAddress((void**)&padh, g_padh);
    cudaGetSymbolAddress((void**)&wh,   g_wh);

    cudaFuncSetAttribute(hgemm_k<1, true>,  cudaFuncAttributeMaxDynamicSharedMemorySize, HSME);
    cudaFuncSetAttribute(hgemm_k<2, true>,  cudaFuncAttributeMaxDynamicSharedMemorySize, HSME);
    cudaFuncSetAttribute(hgemm_k<1, false>, cudaFuncAttributeMaxDynamicSharedMemorySize, HSME);
    cudaFuncSetAttribute(hgemm_k<2, false>, cudaFuncAttributeMaxDynamicSharedMemorySize, HSME);
    cudaFuncSetAttribute(hgemm_ln_k<true, true>,
                         cudaFuncAttributeMaxDynamicSharedMemorySize, LN_SMEM);
    cudaFuncSetAttribute(hgemm_ln_k<false, true>,
                         cudaFuncAttributeMaxDynamicSharedMemorySize, LN_SMEM);
    cudaFuncSetAttribute(hgemm_ln_k<true, false>,
                         cudaFuncAttributeMaxDynamicSharedMemorySize, LN_SMEM);
    cudaFuncSetAttribute(hgemm_ln_k<false, false>,
                         cudaFuncAttributeMaxDynamicSharedMemorySize, LN_SMEM);
    cudaFuncSetAttribute(attn_k<LW, true>,
                         cudaFuncAttributeMaxDynamicSharedMemorySize, LW * 512 * 4);
    cudaFuncSetAttribute(attn_k<MAXW, false>,
                         cudaFuncAttributeMaxDynamicSharedMemorySize, MAXW * 512 * 4);

    auto WC = [&](const float* W, size_t off, int K, int N) {
        wconv_k<<<(K * N + 255) / 256, 256>>>(W, wh + off, K, N);
    };

    // ===== block 1 (char transformer, compacted rows) =====
    scan_k<<<1, 1024>>>(toks);                                                 // 0
    WC(we_qkv, 0, D, 3 * D);                                                   // 1
    WC(we_o, 196608, D, D);                                                    // 2
    embed2_k<<<NW, 256>>>(toks, we_emb, x, xh);                                // 3
    ztail_k<<<128, 256>>>(x, xh, ah, hh);                                      // 4
    hgemm_k<2, true><<<dim3(6, M1 / 128), 256, HSME>>>(xh, wh, qkvh, M1, 3 * D, D); // 5 (profiled)
    attn_k<LW, true><<<NW, 256, LW * 512 * 4>>>(qkvh, ah);
    hgemm_ln_k<true, true><<<M1 / 64, 256, LN_SMEM>>>(ah, wh + 196608, x, h, hh, M1, D);
    WC(we_ff1, 262144, D, DFF);
    hgemm_k<1, true><<<dim3(8, M1 / 128), 256, HSME>>>(hh, wh + 262144, ffh, M1, DFF, D);
    WC(we_ff2, 524288, DFF, D);
    hgemm_ln_k<false, true><<<M1 / 64, 256, LN_SMEM>>>(ffh, wh + 524288, h, x, nullptr, M1, DFF);

    // ===== pool words -> padded [NC, MAXW, D] =====
    zero2_k<<<(M2 * D + 255) / 256, 256>>>(pad, padh, M2 * D);
    pool2_k<<<NW, 256>>>(x, cid, wpos, pad, padh);

    // ===== block 2 (name transformer, dense 16384 rows) =====
    WC(ne_qkv, 786432, D, 3 * D);
    hgemm_k<2, false><<<dim3(6, M2 / 128), 256, HSME>>>(padh, wh + 786432, qkvh, M2, 3 * D, D);
    attn_k<MAXW, false><<<NC, 256, MAXW * 512 * 4>>>(qkvh, ah);
    WC(ne_o, 983040, D, D);
    hgemm_ln_k<true, false><<<M2 / 64, 256, LN_SMEM>>>(ah, wh + 983040, pad, h, hh, M2, D);
    WC(ne_ff1, 1048576, D, DFF);
    hgemm_k<1, false><<<dim3(8, M2 / 128), 256, HSME>>>(hh, wh + 1048576, ffh, M2, DFF, D);
    WC(ne_ff2, 1310720, DFF, D);
    hgemm_ln_k<false, false><<<M2 / 64, 256, LN_SMEM>>>(ffh, wh + 1310720, h, nf, nullptr, M2, DFF);

    // ===== final pooling -> output =====
    final_k<<<NC, 256>>>(nf, pad, out);
}